// round 11
// baseline (speedup 1.0000x reference)
#include <cuda_runtime.h>
#include <cuda_bf16.h>
#include <cuda_fp16.h>
#include <stdint.h>
#include <math.h>

#define B_ 4
#define T_ 2048
#define C_ 1024
#define H_ 16
#define D_ 64
#define M_ (B_*T_)   // 8192

// ---------------------------------------------------------------------------
// Scratch (allocation-free __device__ globals) — all fp16 hi/lo splits
// ---------------------------------------------------------------------------
__device__ unsigned short g_qkvh[25165824];    // qkv hi fp16 [8192][3072]
__device__ unsigned short g_qkvl[25165824];    // qkv lo
__device__ unsigned short g_xh[8388608];       // x hi fp16 [8192][1024]
__device__ unsigned short g_xl[8388608];
__device__ unsigned short g_wqkvh[3145728];    // w_qkv^T hi fp16 [3072][1024]
__device__ unsigned short g_wprojh[1048576];   // w_proj^T hi fp16 [1024][1024]
__device__ unsigned short g_atth[8388608];     // attention out hi fp16 [8192][1024]
__device__ unsigned short g_attl[8388608];

// ---------------------------------------------------------------------------
// Helpers (sm_103 baseline: ldmatrix, mma.sync, cp.async)
// ---------------------------------------------------------------------------
__device__ __forceinline__ uint32_t smem_u32(const void* p) {
    uint32_t a;
    asm("{ .reg .u64 t; cvta.to.shared.u64 t, %1; cvt.u32.u64 %0, t; }"
        : "=r"(a) : "l"(p));
    return a;
}

__device__ __forceinline__ void ldsm_x4(uint32_t& r0, uint32_t& r1,
                                        uint32_t& r2, uint32_t& r3, uint32_t a) {
    asm volatile("ldmatrix.sync.aligned.m8n8.x4.shared.b16 {%0,%1,%2,%3}, [%4];"
                 : "=r"(r0), "=r"(r1), "=r"(r2), "=r"(r3) : "r"(a));
}

__device__ __forceinline__ void ldsm_x2(uint32_t& r0, uint32_t& r1, uint32_t a) {
    asm volatile("ldmatrix.sync.aligned.m8n8.x2.shared.b16 {%0,%1}, [%2];"
                 : "=r"(r0), "=r"(r1) : "r"(a));
}

__device__ __forceinline__ void ldsm_x4t(uint32_t* r, uint32_t a) {
    asm volatile("ldmatrix.sync.aligned.m8n8.x4.trans.shared.b16 {%0,%1,%2,%3}, [%4];"
                 : "=r"(r[0]), "=r"(r[1]), "=r"(r[2]), "=r"(r[3]) : "r"(a));
}

// fp16 MMA, fp32 accumulate
__device__ __forceinline__ void mma16816h(float* c, const uint32_t* A, const uint32_t* Bv) {
    asm volatile(
        "mma.sync.aligned.m16n8k16.row.col.f32.f16.f16.f32 "
        "{%0,%1,%2,%3}, {%4,%5,%6,%7}, {%8,%9}, {%0,%1,%2,%3};"
        : "+f"(c[0]), "+f"(c[1]), "+f"(c[2]), "+f"(c[3])
        : "r"(A[0]), "r"(A[1]), "r"(A[2]), "r"(A[3]), "r"(Bv[0]), "r"(Bv[1]));
}

__device__ __forceinline__ void cp16(uint32_t dst, const void* src) {
    asm volatile("cp.async.cg.shared.global [%0], [%1], 16;" :: "r"(dst), "l"(src));
}
#define CP_COMMIT() asm volatile("cp.async.commit_group;" ::: "memory")
#define CP_WAIT0()  asm volatile("cp.async.wait_group 0;" ::: "memory")

// pack two fp32 -> f16x2 {lo=p0, hi=p1}
__device__ __forceinline__ uint32_t pack_f16(float p0, float p1) {
    uint32_t r;
    asm("cvt.rn.f16x2.f32 %0, %1, %2;" : "=r"(r) : "f"(p1), "f"(p0));
    return r;
}

// split pair -> f16x2 hi + f16x2 residual
__device__ __forceinline__ void mk2h(float p0, float p1, uint32_t& hi, uint32_t& lo) {
    uint32_t h = pack_f16(p0, p1);
    __half2 hh = *reinterpret_cast<__half2*>(&h);
    float r0 = p0 - __low2float(hh);
    float r1 = p1 - __high2float(hh);
    hi = h;
    lo = pack_f16(r0, r1);
}

__device__ __forceinline__ void split2h(float x, unsigned short& hh, unsigned short& ll) {
    __half hb = __float2half_rn(x);
    hh = reinterpret_cast<unsigned short&>(hb);
    float r = x - __half2float(hb);
    __half lb = __float2half_rn(r);
    ll = reinterpret_cast<unsigned short&>(lb);
}

// ---------------------------------------------------------------------------
// Prep kernels (fp16 splits)
// ---------------------------------------------------------------------------
__global__ void __launch_bounds__(256) pack_split_kernel(
    const float* __restrict__ src, unsigned short* __restrict__ hi,
    unsigned short* __restrict__ lo)
{
    int i = blockIdx.x * 256 + threadIdx.x;
    float4 v = ((const float4*)src)[i];
    unsigned short h[4], l[4];
    split2h(v.x, h[0], l[0]); split2h(v.y, h[1], l[1]);
    split2h(v.z, h[2], l[2]); split2h(v.w, h[3], l[3]);
    ((uint2*)hi)[i] = make_uint2((uint32_t)h[0] | ((uint32_t)h[1] << 16),
                                 (uint32_t)h[2] | ((uint32_t)h[3] << 16));
    ((uint2*)lo)[i] = make_uint2((uint32_t)l[0] | ((uint32_t)l[1] << 16),
                                 (uint32_t)l[2] | ((uint32_t)l[3] << 16));
}

// w [K,N] fp32 -> wT hi fp16 [N,K] (hi only — 2-term GEMM drops B lo)
__global__ void __launch_bounds__(256) transpose_pack_kernel(
    const float* __restrict__ w, unsigned short* __restrict__ th, int K, int N)
{
    __shared__ float tile[32][33];
    const int k0 = blockIdx.y * 32, n0 = blockIdx.x * 32;
    const int tx = threadIdx.x, ty = threadIdx.y;   // 32 x 8
    #pragma unroll
    for (int i = 0; i < 32; i += 8)
        tile[ty + i][tx] = w[(size_t)(k0 + ty + i) * N + n0 + tx];
    __syncthreads();
    #pragma unroll
    for (int i = 0; i < 32; i += 8) {
        int n = n0 + ty + i;
        int k = k0 + tx;
        __half hv = __float2half_rn(tile[tx][ty + i]);
        th[(size_t)n * K + k] = reinterpret_cast<unsigned short&>(hv);
    }
}

// ---------------------------------------------------------------------------
// 2-term fp16 mma.sync GEMM: out = (Ah+Al) @ Bh^T + bias.
// BM=BN=128, BK=32, 8 warps (2x4), warp tile 64x32, 2-stage cp.async.
// Stage: Ah 8K | Al 8K | Bh 8K = 24KB; 48KB total -> 2 CTAs/SM for
// cross-CTA overlap of barrier/load bubbles with tensor work.
// ---------------------------------------------------------------------------
#define GEMM_SMEM (2*24576)

__global__ void __launch_bounds__(256, 2) gemm_mma_kernel(
    const unsigned short* __restrict__ ah, const unsigned short* __restrict__ al,
    const unsigned short* __restrict__ bh,
    const float* __restrict__ bias, float* __restrict__ outf,
    unsigned short* __restrict__ outh, unsigned short* __restrict__ outl,
    int M, int N, int K)
{
    extern __shared__ char smc[];
    const uint32_t sbase = smem_u32(smc);
    const int tid  = threadIdx.x;
    const int wid  = tid >> 5, lane = tid & 31;
    const int wm   = wid >> 2, wn = wid & 3;
    const int mBase = blockIdx.y * 128;
    const int nBase = blockIdx.x * 128;
    const int nk = K >> 5;

    const int r0c = tid >> 2;
    const int c0c = tid & 3;
    auto sw = [](int r, int c) { return r * 64 + ((c ^ ((r >> 1) & 3)) << 4); };

    auto issue = [&](int ks, int stage) {
        const int kb = ks << 5;
        const unsigned short* gs[3] = { ah, al, bh };
        #pragma unroll
        for (int part = 0; part < 3; part++) {
            const unsigned short* g = gs[part] +
                (size_t)((part < 2) ? mBase : nBase) * K + kb;
            uint32_t pb = sbase + stage * 24576 + part * 8192;
            cp16(pb + sw(r0c,      c0c), g + (size_t)r0c        * K + c0c * 8);
            cp16(pb + sw(r0c + 64, c0c), g + (size_t)(r0c + 64) * K + c0c * 8);
        }
        CP_COMMIT();
    };

    float acc[4][4][4];
    #pragma unroll
    for (int i = 0; i < 4; i++)
        #pragma unroll
        for (int j = 0; j < 4; j++)
            #pragma unroll
            for (int r = 0; r < 4; r++) acc[i][j][r] = 0.f;

    const int la_row = lane & 15;
    const int la_kh  = lane >> 4;
    const int lb_row = lane & 7;
    const int lb_kh  = (lane >> 3) & 1;

    issue(0, 0);

    for (int ks = 0; ks < nk; ks++) {
        const int cur = ks & 1;
        CP_WAIT0();
        __syncthreads();
        if (ks + 1 < nk) issue(ks + 1, cur ^ 1);

        const uint32_t sAh = sbase + cur * 24576;
        const uint32_t sAl = sAh + 8192;
        const uint32_t sBh = sAh + 16384;

        #pragma unroll
        for (int kk = 0; kk < 2; kk++) {
            const int ch_a = kk * 2 + la_kh;
            const int ch_b = kk * 2 + lb_kh;

            uint32_t Ahf[4][4], Bhf[4][2];
            #pragma unroll
            for (int i = 0; i < 4; i++) {
                int row = wm * 64 + i * 16 + la_row;
                ldsm_x4(Ahf[i][0], Ahf[i][1], Ahf[i][2], Ahf[i][3], sAh + sw(row, ch_a));
            }
            #pragma unroll
            for (int j = 0; j < 4; j++) {
                int row = wn * 32 + j * 8 + lb_row;
                ldsm_x2(Bhf[j][0], Bhf[j][1], sBh + sw(row, ch_b));
            }
            #pragma unroll
            for (int i = 0; i < 4; i++)
                #pragma unroll
                for (int j = 0; j < 4; j++) mma16816h(acc[i][j], Ahf[i], Bhf[j]);

            // Al x Bh (reuse Bh fragments)
            uint32_t Alf[4][4];
            #pragma unroll
            for (int i = 0; i < 4; i++) {
                int row = wm * 64 + i * 16 + la_row;
                ldsm_x4(Alf[i][0], Alf[i][1], Alf[i][2], Alf[i][3], sAl + sw(row, ch_a));
            }
            #pragma unroll
            for (int i = 0; i < 4; i++)
                #pragma unroll
                for (int j = 0; j < 4; j++) mma16816h(acc[i][j], Alf[i], Bhf[j]);
        }
    }

    // Epilogue
    const int g = lane >> 2, q = lane & 3;
    #pragma unroll
    for (int i = 0; i < 4; i++) {
        const int row0 = mBase + wm * 64 + i * 16 + g;
        #pragma unroll
        for (int j = 0; j < 4; j++) {
            const int col = nBase + wn * 32 + j * 8 + q * 2;
            float2 bb = *(const float2*)(bias + col);
            float v0x = acc[i][j][0] + bb.x, v0y = acc[i][j][1] + bb.y;
            float v1x = acc[i][j][2] + bb.x, v1y = acc[i][j][3] + bb.y;
            if (outh) {
                uint32_t h0, l0, h1, l1;
                mk2h(v0x, v0y, h0, l0);
                mk2h(v1x, v1y, h1, l1);
                *(uint32_t*)(outh + (size_t)row0 * N + col)       = h0;
                *(uint32_t*)(outl + (size_t)row0 * N + col)       = l0;
                *(uint32_t*)(outh + (size_t)(row0 + 8) * N + col) = h1;
                *(uint32_t*)(outl + (size_t)(row0 + 8) * N + col) = l1;
            } else {
                *(float2*)(outf + (size_t)row0 * N + col)       = make_float2(v0x, v0y);
                *(float2*)(outf + (size_t)(row0 + 8) * N + col) = make_float2(v1x, v1y);
            }
        }
    }
}

// ---------------------------------------------------------------------------
// Tensor-core flash attention (causal, fp16). Unchanged from R10 win.
// ---------------------------------------------------------------------------
#define ATTN_SMEM (32768 + 2*24576)

__global__ void __launch_bounds__(256, 2) attn_mma_kernel(
    const unsigned short* __restrict__ qkvh,
    const unsigned short* __restrict__ qkvl,
    unsigned short* __restrict__ atth,
    unsigned short* __restrict__ attl)
{
    extern __shared__ char smc[];
    const uint32_t sb = smem_u32(smc);
    const int tid = threadIdx.x, lane = tid & 31, w = tid >> 5;
    const int bh = blockIdx.y, b = bh >> 4, hd = bh & 15;
    const int qb = (int)gridDim.x - 1 - (int)blockIdx.x;   // big blocks first
    const int q0 = qb * 128;
    const int nkt = 2 * qb + 2;

    const size_t base = (size_t)b * T_ * 3072 + hd * 64;
    const unsigned short* qh = qkvh + base;
    const unsigned short* qlp = qkvl + base;
    const unsigned short* kh = qh + 1024;
    const unsigned short* vh = qh + 2048;
    const unsigned short* vl = qlp + 2048;

    const uint32_t sQh = sb, sQl = sb + 16384;
    auto stage0 = [&](int s) { return sb + 32768 + s * 24576; };
    auto off = [](int r, int c) { return r * 128 + ((c ^ (r & 7)) << 4); };

    auto issue_kv = [&](int kt, int s) {
        uint32_t sn = stage0(s);
        const size_t kb = (size_t)kt * 64;
        #pragma unroll
        for (int i = 0; i < 2; i++) {
            int idx = i * 256 + tid;
            int r = idx >> 3, c = idx & 7;
            const size_t g = (kb + r) * 3072 + c * 8;
            cp16(sn +         off(r, c), kh + g);
            cp16(sn + 8192 +  off(r, c), vh + g);
            cp16(sn + 16384 + off(r, c), vl + g);
        }
        CP_COMMIT();
    };

    // prologue: Q (hi+lo) + K/V tile 0, one commit group
    #pragma unroll
    for (int i = 0; i < 4; i++) {
        int idx = i * 256 + tid;
        int r = idx >> 3, c = idx & 7;
        const size_t g = (size_t)(q0 + r) * 3072 + c * 8;
        cp16(sQh + off(r, c), qh + g);
        cp16(sQl + off(r, c), qlp + g);
    }
    issue_kv(0, 0);

    float O[8][4], s[8][4];
    #pragma unroll
    for (int j = 0; j < 8; j++) { O[j][0] = O[j][1] = O[j][2] = O[j][3] = 0.f; }
    float m_lo = -1e30f, m_hi = -1e30f, l_lo = 0.f, l_hi = 0.f;

    const int la_row = lane & 15, la_kh = lane >> 4;
    const int kb_row = ((lane >> 4) << 3) + (lane & 7);
    const int kb_ch  = (lane >> 3) & 1;
    const int vb_row = (((lane >> 3) & 1) << 3) + (lane & 7);
    const int vb_ch  = lane >> 4;
    const int rowq_lo = q0 + w * 16 + (lane >> 2);
    const float SC = 0.125f * 1.4426950408889634f;   // scale * log2(e)

    for (int kt = 0; kt < nkt; kt++) {
        const int cur = kt & 1;
        CP_WAIT0();
        __syncthreads();
        if (kt + 1 < nkt) issue_kv(kt + 1, cur ^ 1);

        const int k0 = kt * 64;
        const bool active = (k0 <= q0 + w * 16 + 15);
        if (active) {
            const uint32_t cK  = stage0(cur);
            const uint32_t cV  = cK + 8192;
            const uint32_t cVl = cK + 16384;

            // ---- S = Q K^T (fp16 2-term: QhKh + QlKh) ----
            #pragma unroll
            for (int j = 0; j < 8; j++) { s[j][0] = s[j][1] = s[j][2] = s[j][3] = 0.f; }
            #pragma unroll
            for (int kk = 0; kk < 4; kk++) {
                uint32_t aqh[4], aql[4];
                ldsm_x4(aqh[0], aqh[1], aqh[2], aqh[3],
                        sQh + off(w * 16 + la_row, 2 * kk + la_kh));
                ldsm_x4(aql[0], aql[1], aql[2], aql[3],
                        sQl + off(w * 16 + la_row, 2 * kk + la_kh));
                #pragma unroll
                for (int j2 = 0; j2 < 4; j2++) {
                    uint32_t bk[4];
                    ldsm_x4(bk[0], bk[1], bk[2], bk[3],
                            cK + off(16 * j2 + kb_row, 2 * kk + kb_ch));
                    mma16816h(s[2 * j2],     aqh, bk);
                    mma16816h(s[2 * j2 + 1], aqh, bk + 2);
                    mma16816h(s[2 * j2],     aql, bk);
                    mma16816h(s[2 * j2 + 1], aql, bk + 2);
                }
            }

            // ---- online softmax (exp2 domain) ----
            const bool masked = (k0 + 63 > q0 + w * 16);
            float rm_lo = -1e30f, rm_hi = -1e30f;
            #pragma unroll
            for (int j = 0; j < 8; j++) {
                int colb = k0 + 8 * j + 2 * (lane & 3);
                #pragma unroll
                for (int e = 0; e < 2; e++) {
                    float v = s[j][e] * SC;
                    if (masked && (colb + e) > rowq_lo) v = -1e30f;
                    s[j][e] = v; rm_lo = fmaxf(rm_lo, v);
                    float v2 = s[j][2 + e] * SC;
                    if (masked && (colb + e) > rowq_lo + 8) v2 = -1e30f;
                    s[j][2 + e] = v2; rm_hi = fmaxf(rm_hi, v2);
                }
            }
            rm_lo = fmaxf(rm_lo, __shfl_xor_sync(0xffffffffu, rm_lo, 1));
            rm_lo = fmaxf(rm_lo, __shfl_xor_sync(0xffffffffu, rm_lo, 2));
            rm_hi = fmaxf(rm_hi, __shfl_xor_sync(0xffffffffu, rm_hi, 1));
            rm_hi = fmaxf(rm_hi, __shfl_xor_sync(0xffffffffu, rm_hi, 2));
            float mn_lo = fmaxf(m_lo, rm_lo), mn_hi = fmaxf(m_hi, rm_hi);
            float corr_lo = exp2f(m_lo - mn_lo), corr_hi = exp2f(m_hi - mn_hi);
            m_lo = mn_lo; m_hi = mn_hi;
            float ps_lo = 0.f, ps_hi = 0.f;
            #pragma unroll
            for (int j = 0; j < 8; j++) {
                s[j][0] = exp2f(s[j][0] - mn_lo);
                s[j][1] = exp2f(s[j][1] - mn_lo);
                s[j][2] = exp2f(s[j][2] - mn_hi);
                s[j][3] = exp2f(s[j][3] - mn_hi);
                ps_lo += s[j][0] + s[j][1];
                ps_hi += s[j][2] + s[j][3];
            }
            ps_lo += __shfl_xor_sync(0xffffffffu, ps_lo, 1);
            ps_lo += __shfl_xor_sync(0xffffffffu, ps_lo, 2);
            ps_hi += __shfl_xor_sync(0xffffffffu, ps_hi, 1);
            ps_hi += __shfl_xor_sync(0xffffffffu, ps_hi, 2);
            l_lo = l_lo * corr_lo + ps_lo;
            l_hi = l_hi * corr_hi + ps_hi;
            #pragma unroll
            for (int j = 0; j < 8; j++) {
                O[j][0] *= corr_lo; O[j][1] *= corr_lo;
                O[j][2] *= corr_hi; O[j][3] *= corr_hi;
            }

            // ---- O += P V (P fp16 single; V fp16 2-term) ----
            #pragma unroll
            for (int t = 0; t < 4; t++) {
                uint32_t ph[4];
                ph[0] = pack_f16(s[2 * t][0],     s[2 * t][1]);
                ph[1] = pack_f16(s[2 * t][2],     s[2 * t][3]);
                ph[2] = pack_f16(s[2 * t + 1][0], s[2 * t + 1][1]);
                ph[3] = pack_f16(s[2 * t + 1][2], s[2 * t + 1][3]);
                #pragma unroll
                for (int j2 = 0; j2 < 4; j2++) {
                    uint32_t bv[4];
                    ldsm_x4t(bv, cV + off(16 * t + vb_row, 2 * j2 + vb_ch));
                    mma16816h(O[2 * j2],     ph, bv);
                    mma16816h(O[2 * j2 + 1], ph, bv + 2);
                    ldsm_x4t(bv, cVl + off(16 * t + vb_row, 2 * j2 + vb_ch));
                    mma16816h(O[2 * j2],     ph, bv);
                    mma16816h(O[2 * j2 + 1], ph, bv + 2);
                }
            }
        }
    }

    // ---- epilogue: normalize, split-fp16, write ----
    const float inv_lo = 1.f / l_lo, inv_hi = 1.f / l_hi;
    const size_t row_lo = (size_t)(b * T_) + q0 + w * 16 + (lane >> 2);
    const int colb = hd * 64 + 2 * (lane & 3);
    #pragma unroll
    for (int j = 0; j < 8; j++) {
        const int col = colb + 8 * j;
        uint32_t h0, l0, h1, l1;
        mk2h(O[j][0] * inv_lo, O[j][1] * inv_lo, h0, l0);
        mk2h(O[j][2] * inv_hi, O[j][3] * inv_hi, h1, l1);
        *(uint32_t*)(atth + row_lo * C_ + col)       = h0;
        *(uint32_t*)(attl + row_lo * C_ + col)       = l0;
        *(uint32_t*)(atth + (row_lo + 8) * C_ + col) = h1;
        *(uint32_t*)(attl + (row_lo + 8) * C_ + col) = l1;
    }
}

// ---------------------------------------------------------------------------
extern "C" void kernel_launch(void* const* d_in, const int* in_sizes, int n_in,
                              void* d_out, int out_size)
{
    const float* x      = (const float*)d_in[0];
    const float* w_qkv  = (const float*)d_in[1];
    const float* b_qkv  = (const float*)d_in[2];
    const float* w_proj = (const float*)d_in[3];
    const float* b_proj = (const float*)d_in[4];
    float* out = (float*)d_out;

    unsigned short *qvh, *qvl, *xh, *xl, *wqh, *wph, *ath, *atl;
    cudaGetSymbolAddress((void**)&qvh, g_qkvh);
    cudaGetSymbolAddress((void**)&qvl, g_qkvl);
    cudaGetSymbolAddress((void**)&xh, g_xh);
    cudaGetSymbolAddress((void**)&xl, g_xl);
    cudaGetSymbolAddress((void**)&wqh, g_wqkvh);
    cudaGetSymbolAddress((void**)&wph, g_wprojh);
    cudaGetSymbolAddress((void**)&ath, g_atth);
    cudaGetSymbolAddress((void**)&atl, g_attl);

    cudaFuncSetAttribute(gemm_mma_kernel,
                         cudaFuncAttributeMaxDynamicSharedMemorySize, GEMM_SMEM);
    cudaFuncSetAttribute(attn_mma_kernel,
                         cudaFuncAttributeMaxDynamicSharedMemorySize, ATTN_SMEM);

    // 0) pack inputs to fp16 splits (weights: hi only)
    pack_split_kernel<<<M_*C_/1024, 256>>>(x, xh, xl);
    transpose_pack_kernel<<<dim3(3*C_/32, C_/32), dim3(32, 8)>>>(w_qkv, wqh, C_, 3*C_);
    transpose_pack_kernel<<<dim3(C_/32, C_/32), dim3(32, 8)>>>(w_proj, wph, C_, C_);

    // 1) qkv = x @ w_qkv + b_qkv  -> split-fp16 qkv
    gemm_mma_kernel<<<dim3(3*C_/128, M_/128), 256, GEMM_SMEM>>>(
        xh, xl, wqh, b_qkv, nullptr, qvh, qvl, M_, 3*C_, C_);

    // 2) tensor-core causal flash attention (fp16) -> split-fp16 att
    attn_mma_kernel<<<dim3(T_/128, B_*H_), 256, ATTN_SMEM>>>(qvh, qvl, ath, atl);

    // 3) out = att @ w_proj + b_proj  -> fp32
    gemm_mma_kernel<<<dim3(C_/128, M_/128), 256, GEMM_SMEM>>>(
        ath, atl, wph, b_proj, out, nullptr, nullptr, M_, C_, C_);
}

// round 12
// speedup vs baseline: 1.3032x; 1.3032x over previous
#include <cuda_runtime.h>
#include <cuda_bf16.h>
#include <cuda_fp16.h>
#include <stdint.h>
#include <math.h>

#define B_ 4
#define T_ 2048
#define C_ 1024
#define H_ 16
#define D_ 64
#define M_ (B_*T_)   // 8192

// ---------------------------------------------------------------------------
// Scratch (allocation-free __device__ globals) — all fp16 hi/lo splits
// ---------------------------------------------------------------------------
__device__ unsigned short g_qkvh[25165824];    // qkv hi fp16 [8192][3072]
__device__ unsigned short g_qkvl[25165824];    // qkv lo
__device__ unsigned short g_xh[8388608];       // x hi fp16 [8192][1024]
__device__ unsigned short g_xl[8388608];
__device__ unsigned short g_wqkvh[3145728];    // w_qkv^T hi fp16 [3072][1024]
__device__ unsigned short g_wprojh[1048576];   // w_proj^T hi fp16 [1024][1024]
__device__ unsigned short g_atth[8388608];     // attention out hi fp16 [8192][1024]
__device__ unsigned short g_attl[8388608];

// ---------------------------------------------------------------------------
// Helpers (sm_103 baseline: ldmatrix, mma.sync, cp.async)
// ---------------------------------------------------------------------------
__device__ __forceinline__ uint32_t smem_u32(const void* p) {
    uint32_t a;
    asm("{ .reg .u64 t; cvta.to.shared.u64 t, %1; cvt.u32.u64 %0, t; }"
        : "=r"(a) : "l"(p));
    return a;
}

__device__ __forceinline__ void ldsm_x4(uint32_t& r0, uint32_t& r1,
                                        uint32_t& r2, uint32_t& r3, uint32_t a) {
    asm volatile("ldmatrix.sync.aligned.m8n8.x4.shared.b16 {%0,%1,%2,%3}, [%4];"
                 : "=r"(r0), "=r"(r1), "=r"(r2), "=r"(r3) : "r"(a));
}

__device__ __forceinline__ void ldsm_x2(uint32_t& r0, uint32_t& r1, uint32_t a) {
    asm volatile("ldmatrix.sync.aligned.m8n8.x2.shared.b16 {%0,%1}, [%2];"
                 : "=r"(r0), "=r"(r1) : "r"(a));
}

__device__ __forceinline__ void ldsm_x4t(uint32_t* r, uint32_t a) {
    asm volatile("ldmatrix.sync.aligned.m8n8.x4.trans.shared.b16 {%0,%1,%2,%3}, [%4];"
                 : "=r"(r[0]), "=r"(r[1]), "=r"(r[2]), "=r"(r[3]) : "r"(a));
}

// fp16 MMA, fp32 accumulate
__device__ __forceinline__ void mma16816h(float* c, const uint32_t* A, const uint32_t* Bv) {
    asm volatile(
        "mma.sync.aligned.m16n8k16.row.col.f32.f16.f16.f32 "
        "{%0,%1,%2,%3}, {%4,%5,%6,%7}, {%8,%9}, {%0,%1,%2,%3};"
        : "+f"(c[0]), "+f"(c[1]), "+f"(c[2]), "+f"(c[3])
        : "r"(A[0]), "r"(A[1]), "r"(A[2]), "r"(A[3]), "r"(Bv[0]), "r"(Bv[1]));
}

__device__ __forceinline__ void cp16(uint32_t dst, const void* src) {
    asm volatile("cp.async.cg.shared.global [%0], [%1], 16;" :: "r"(dst), "l"(src));
}
#define CP_COMMIT() asm volatile("cp.async.commit_group;" ::: "memory")
#define CP_WAIT0()  asm volatile("cp.async.wait_group 0;" ::: "memory")

// pack two fp32 -> f16x2 {lo=p0, hi=p1}
__device__ __forceinline__ uint32_t pack_f16(float p0, float p1) {
    uint32_t r;
    asm("cvt.rn.f16x2.f32 %0, %1, %2;" : "=r"(r) : "f"(p1), "f"(p0));
    return r;
}

// split pair -> f16x2 hi + f16x2 residual
__device__ __forceinline__ void mk2h(float p0, float p1, uint32_t& hi, uint32_t& lo) {
    uint32_t h = pack_f16(p0, p1);
    __half2 hh = *reinterpret_cast<__half2*>(&h);
    float r0 = p0 - __low2float(hh);
    float r1 = p1 - __high2float(hh);
    hi = h;
    lo = pack_f16(r0, r1);
}

__device__ __forceinline__ void split2h(float x, unsigned short& hh, unsigned short& ll) {
    __half hb = __float2half_rn(x);
    hh = reinterpret_cast<unsigned short&>(hb);
    float r = x - __half2float(hb);
    __half lb = __float2half_rn(r);
    ll = reinterpret_cast<unsigned short&>(lb);
}

// ---------------------------------------------------------------------------
// Prep kernels (fp16 splits)
// ---------------------------------------------------------------------------
__global__ void __launch_bounds__(256) pack_split_kernel(
    const float* __restrict__ src, unsigned short* __restrict__ hi,
    unsigned short* __restrict__ lo)
{
    int i = blockIdx.x * 256 + threadIdx.x;
    float4 v = ((const float4*)src)[i];
    unsigned short h[4], l[4];
    split2h(v.x, h[0], l[0]); split2h(v.y, h[1], l[1]);
    split2h(v.z, h[2], l[2]); split2h(v.w, h[3], l[3]);
    ((uint2*)hi)[i] = make_uint2((uint32_t)h[0] | ((uint32_t)h[1] << 16),
                                 (uint32_t)h[2] | ((uint32_t)h[3] << 16));
    ((uint2*)lo)[i] = make_uint2((uint32_t)l[0] | ((uint32_t)l[1] << 16),
                                 (uint32_t)l[2] | ((uint32_t)l[3] << 16));
}

// w [K,N] fp32 -> wT hi fp16 [N,K] (hi only — 2-term GEMM drops B lo)
__global__ void __launch_bounds__(256) transpose_pack_kernel(
    const float* __restrict__ w, unsigned short* __restrict__ th, int K, int N)
{
    __shared__ float tile[32][33];
    const int k0 = blockIdx.y * 32, n0 = blockIdx.x * 32;
    const int tx = threadIdx.x, ty = threadIdx.y;   // 32 x 8
    #pragma unroll
    for (int i = 0; i < 32; i += 8)
        tile[ty + i][tx] = w[(size_t)(k0 + ty + i) * N + n0 + tx];
    __syncthreads();
    #pragma unroll
    for (int i = 0; i < 32; i += 8) {
        int n = n0 + ty + i;
        int k = k0 + tx;
        __half hv = __float2half_rn(tile[tx][ty + i]);
        th[(size_t)n * K + k] = reinterpret_cast<unsigned short&>(hv);
    }
}

// ---------------------------------------------------------------------------
// 2-term fp16 mma.sync GEMM: out = (Ah+Al) @ Bh^T + bias.
// EXACT R10 structure (measured best: 302us QKV). 2 CTAs/SM occur naturally.
// ---------------------------------------------------------------------------
#define GEMM_SMEM (2*24576)

__global__ void __launch_bounds__(256) gemm_mma_kernel(
    const unsigned short* __restrict__ ah, const unsigned short* __restrict__ al,
    const unsigned short* __restrict__ bh,
    const float* __restrict__ bias, float* __restrict__ outf,
    unsigned short* __restrict__ outh, unsigned short* __restrict__ outl,
    int M, int N, int K)
{
    extern __shared__ char smc[];
    const uint32_t sbase = smem_u32(smc);
    const int tid  = threadIdx.x;
    const int wid  = tid >> 5, lane = tid & 31;
    const int wm   = wid >> 2, wn = wid & 3;
    const int mBase = blockIdx.y * 128;
    const int nBase = blockIdx.x * 128;
    const int nk = K >> 5;

    const int r0c = tid >> 2;
    const int c0c = tid & 3;
    auto sw = [](int r, int c) { return r * 64 + ((c ^ ((r >> 1) & 3)) << 4); };

    auto issue = [&](int ks, int stage) {
        const int kb = ks << 5;
        const unsigned short* gs[3] = { ah, al, bh };
        #pragma unroll
        for (int part = 0; part < 3; part++) {
            const unsigned short* g = gs[part] +
                (size_t)((part < 2) ? mBase : nBase) * K + kb;
            uint32_t pb = sbase + stage * 24576 + part * 8192;
            cp16(pb + sw(r0c,      c0c), g + (size_t)r0c        * K + c0c * 8);
            cp16(pb + sw(r0c + 64, c0c), g + (size_t)(r0c + 64) * K + c0c * 8);
        }
        CP_COMMIT();
    };

    float acc[4][4][4];
    #pragma unroll
    for (int i = 0; i < 4; i++)
        #pragma unroll
        for (int j = 0; j < 4; j++)
            #pragma unroll
            for (int r = 0; r < 4; r++) acc[i][j][r] = 0.f;

    const int la_row = lane & 15;
    const int la_kh  = lane >> 4;
    const int lb_row = lane & 7;
    const int lb_kh  = (lane >> 3) & 1;

    issue(0, 0);

    for (int ks = 0; ks < nk; ks++) {
        const int cur = ks & 1;
        CP_WAIT0();
        __syncthreads();
        if (ks + 1 < nk) issue(ks + 1, cur ^ 1);

        const uint32_t sAh = sbase + cur * 24576;
        const uint32_t sAl = sAh + 8192;
        const uint32_t sBh = sAh + 16384;

        #pragma unroll
        for (int kk = 0; kk < 2; kk++) {
            const int ch_a = kk * 2 + la_kh;
            const int ch_b = kk * 2 + lb_kh;

            uint32_t Ahf[4][4], Bhf[4][2];
            #pragma unroll
            for (int i = 0; i < 4; i++) {
                int row = wm * 64 + i * 16 + la_row;
                ldsm_x4(Ahf[i][0], Ahf[i][1], Ahf[i][2], Ahf[i][3], sAh + sw(row, ch_a));
            }
            #pragma unroll
            for (int j = 0; j < 4; j++) {
                int row = wn * 32 + j * 8 + lb_row;
                ldsm_x2(Bhf[j][0], Bhf[j][1], sBh + sw(row, ch_b));
            }
            #pragma unroll
            for (int i = 0; i < 4; i++)
                #pragma unroll
                for (int j = 0; j < 4; j++) mma16816h(acc[i][j], Ahf[i], Bhf[j]);

            // Al x Bh (reuse Bh fragments)
            uint32_t Alf[4][4];
            #pragma unroll
            for (int i = 0; i < 4; i++) {
                int row = wm * 64 + i * 16 + la_row;
                ldsm_x4(Alf[i][0], Alf[i][1], Alf[i][2], Alf[i][3], sAl + sw(row, ch_a));
            }
            #pragma unroll
            for (int i = 0; i < 4; i++)
                #pragma unroll
                for (int j = 0; j < 4; j++) mma16816h(acc[i][j], Alf[i], Bhf[j]);
        }
    }

    // Epilogue
    const int g = lane >> 2, q = lane & 3;
    #pragma unroll
    for (int i = 0; i < 4; i++) {
        const int row0 = mBase + wm * 64 + i * 16 + g;
        #pragma unroll
        for (int j = 0; j < 4; j++) {
            const int col = nBase + wn * 32 + j * 8 + q * 2;
            float2 bb = *(const float2*)(bias + col);
            float v0x = acc[i][j][0] + bb.x, v0y = acc[i][j][1] + bb.y;
            float v1x = acc[i][j][2] + bb.x, v1y = acc[i][j][3] + bb.y;
            if (outh) {
                uint32_t h0, l0, h1, l1;
                mk2h(v0x, v0y, h0, l0);
                mk2h(v1x, v1y, h1, l1);
                *(uint32_t*)(outh + (size_t)row0 * N + col)       = h0;
                *(uint32_t*)(outl + (size_t)row0 * N + col)       = l0;
                *(uint32_t*)(outh + (size_t)(row0 + 8) * N + col) = h1;
                *(uint32_t*)(outl + (size_t)(row0 + 8) * N + col) = l1;
            } else {
                *(float2*)(outf + (size_t)row0 * N + col)       = make_float2(v0x, v0y);
                *(float2*)(outf + (size_t)(row0 + 8) * N + col) = make_float2(v1x, v1y);
            }
        }
    }
}

// ---------------------------------------------------------------------------
// Tensor-core flash attention (causal, fp16).
// S = QhKh + QlKh (2-term); PV = Ph*Vh (V single fp16 — Vl dropped, err ~2.4e-4).
// Stage: Kh 8K | Vh 8K = 16KB; smem 32 + 2*16 = 64KB.
// ---------------------------------------------------------------------------
#define ATTN_SMEM (32768 + 2*16384)

__global__ void __launch_bounds__(256, 2) attn_mma_kernel(
    const unsigned short* __restrict__ qkvh,
    const unsigned short* __restrict__ qkvl,
    unsigned short* __restrict__ atth,
    unsigned short* __restrict__ attl)
{
    extern __shared__ char smc[];
    const uint32_t sb = smem_u32(smc);
    const int tid = threadIdx.x, lane = tid & 31, w = tid >> 5;
    const int bh = blockIdx.y, b = bh >> 4, hd = bh & 15;
    const int qb = (int)gridDim.x - 1 - (int)blockIdx.x;   // big blocks first
    const int q0 = qb * 128;
    const int nkt = 2 * qb + 2;

    const size_t base = (size_t)b * T_ * 3072 + hd * 64;
    const unsigned short* qh = qkvh + base;
    const unsigned short* qlp = qkvl + base;
    const unsigned short* kh = qh + 1024;
    const unsigned short* vh = qh + 2048;

    const uint32_t sQh = sb, sQl = sb + 16384;
    auto stage0 = [&](int s) { return sb + 32768 + s * 16384; };
    auto off = [](int r, int c) { return r * 128 + ((c ^ (r & 7)) << 4); };

    auto issue_kv = [&](int kt, int s) {
        uint32_t sn = stage0(s);
        const size_t kb = (size_t)kt * 64;
        #pragma unroll
        for (int i = 0; i < 2; i++) {
            int idx = i * 256 + tid;
            int r = idx >> 3, c = idx & 7;
            const size_t g = (kb + r) * 3072 + c * 8;
            cp16(sn +        off(r, c), kh + g);
            cp16(sn + 8192 + off(r, c), vh + g);
        }
        CP_COMMIT();
    };

    // prologue: Q (hi+lo) + K/V tile 0, one commit group
    #pragma unroll
    for (int i = 0; i < 4; i++) {
        int idx = i * 256 + tid;
        int r = idx >> 3, c = idx & 7;
        const size_t g = (size_t)(q0 + r) * 3072 + c * 8;
        cp16(sQh + off(r, c), qh + g);
        cp16(sQl + off(r, c), qlp + g);
    }
    issue_kv(0, 0);

    float O[8][4], s[8][4];
    #pragma unroll
    for (int j = 0; j < 8; j++) { O[j][0] = O[j][1] = O[j][2] = O[j][3] = 0.f; }
    float m_lo = -1e30f, m_hi = -1e30f, l_lo = 0.f, l_hi = 0.f;

    const int la_row = lane & 15, la_kh = lane >> 4;
    const int kb_row = ((lane >> 4) << 3) + (lane & 7);
    const int kb_ch  = (lane >> 3) & 1;
    const int vb_row = (((lane >> 3) & 1) << 3) + (lane & 7);
    const int vb_ch  = lane >> 4;
    const int rowq_lo = q0 + w * 16 + (lane >> 2);
    const float SC = 0.125f * 1.4426950408889634f;   // scale * log2(e)

    for (int kt = 0; kt < nkt; kt++) {
        const int cur = kt & 1;
        CP_WAIT0();
        __syncthreads();
        if (kt + 1 < nkt) issue_kv(kt + 1, cur ^ 1);

        const int k0 = kt * 64;
        const bool active = (k0 <= q0 + w * 16 + 15);
        if (active) {
            const uint32_t cK = stage0(cur);
            const uint32_t cV = cK + 8192;

            // ---- S = Q K^T (fp16 2-term: QhKh + QlKh) ----
            #pragma unroll
            for (int j = 0; j < 8; j++) { s[j][0] = s[j][1] = s[j][2] = s[j][3] = 0.f; }
            #pragma unroll
            for (int kk = 0; kk < 4; kk++) {
                uint32_t aqh[4], aql[4];
                ldsm_x4(aqh[0], aqh[1], aqh[2], aqh[3],
                        sQh + off(w * 16 + la_row, 2 * kk + la_kh));
                ldsm_x4(aql[0], aql[1], aql[2], aql[3],
                        sQl + off(w * 16 + la_row, 2 * kk + la_kh));
                #pragma unroll
                for (int j2 = 0; j2 < 4; j2++) {
                    uint32_t bk[4];
                    ldsm_x4(bk[0], bk[1], bk[2], bk[3],
                            cK + off(16 * j2 + kb_row, 2 * kk + kb_ch));
                    mma16816h(s[2 * j2],     aqh, bk);
                    mma16816h(s[2 * j2 + 1], aqh, bk + 2);
                    mma16816h(s[2 * j2],     aql, bk);
                    mma16816h(s[2 * j2 + 1], aql, bk + 2);
                }
            }

            // ---- online softmax (exp2 domain) ----
            const bool masked = (k0 + 63 > q0 + w * 16);
            float rm_lo = -1e30f, rm_hi = -1e30f;
            #pragma unroll
            for (int j = 0; j < 8; j++) {
                int colb = k0 + 8 * j + 2 * (lane & 3);
                #pragma unroll
                for (int e = 0; e < 2; e++) {
                    float v = s[j][e] * SC;
                    if (masked && (colb + e) > rowq_lo) v = -1e30f;
                    s[j][e] = v; rm_lo = fmaxf(rm_lo, v);
                    float v2 = s[j][2 + e] * SC;
                    if (masked && (colb + e) > rowq_lo + 8) v2 = -1e30f;
                    s[j][2 + e] = v2; rm_hi = fmaxf(rm_hi, v2);
                }
            }
            rm_lo = fmaxf(rm_lo, __shfl_xor_sync(0xffffffffu, rm_lo, 1));
            rm_lo = fmaxf(rm_lo, __shfl_xor_sync(0xffffffffu, rm_lo, 2));
            rm_hi = fmaxf(rm_hi, __shfl_xor_sync(0xffffffffu, rm_hi, 1));
            rm_hi = fmaxf(rm_hi, __shfl_xor_sync(0xffffffffu, rm_hi, 2));
            float mn_lo = fmaxf(m_lo, rm_lo), mn_hi = fmaxf(m_hi, rm_hi);
            float corr_lo = exp2f(m_lo - mn_lo), corr_hi = exp2f(m_hi - mn_hi);
            m_lo = mn_lo; m_hi = mn_hi;
            float ps_lo = 0.f, ps_hi = 0.f;
            #pragma unroll
            for (int j = 0; j < 8; j++) {
                s[j][0] = exp2f(s[j][0] - mn_lo);
                s[j][1] = exp2f(s[j][1] - mn_lo);
                s[j][2] = exp2f(s[j][2] - mn_hi);
                s[j][3] = exp2f(s[j][3] - mn_hi);
                ps_lo += s[j][0] + s[j][1];
                ps_hi += s[j][2] + s[j][3];
            }
            ps_lo += __shfl_xor_sync(0xffffffffu, ps_lo, 1);
            ps_lo += __shfl_xor_sync(0xffffffffu, ps_lo, 2);
            ps_hi += __shfl_xor_sync(0xffffffffu, ps_hi, 1);
            ps_hi += __shfl_xor_sync(0xffffffffu, ps_hi, 2);
            l_lo = l_lo * corr_lo + ps_lo;
            l_hi = l_hi * corr_hi + ps_hi;
            #pragma unroll
            for (int j = 0; j < 8; j++) {
                O[j][0] *= corr_lo; O[j][1] *= corr_lo;
                O[j][2] *= corr_hi; O[j][3] *= corr_hi;
            }

            // ---- O += P V (P fp16 single; V fp16 single) ----
            #pragma unroll
            for (int t = 0; t < 4; t++) {
                uint32_t ph[4];
                ph[0] = pack_f16(s[2 * t][0],     s[2 * t][1]);
                ph[1] = pack_f16(s[2 * t][2],     s[2 * t][3]);
                ph[2] = pack_f16(s[2 * t + 1][0], s[2 * t + 1][1]);
                ph[3] = pack_f16(s[2 * t + 1][2], s[2 * t + 1][3]);
                #pragma unroll
                for (int j2 = 0; j2 < 4; j2++) {
                    uint32_t bv[4];
                    ldsm_x4t(bv, cV + off(16 * t + vb_row, 2 * j2 + vb_ch));
                    mma16816h(O[2 * j2],     ph, bv);
                    mma16816h(O[2 * j2 + 1], ph, bv + 2);
                }
            }
        }
    }

    // ---- epilogue: normalize, split-fp16, write ----
    const float inv_lo = 1.f / l_lo, inv_hi = 1.f / l_hi;
    const size_t row_lo = (size_t)(b * T_) + q0 + w * 16 + (lane >> 2);
    const int colb = hd * 64 + 2 * (lane & 3);
    #pragma unroll
    for (int j = 0; j < 8; j++) {
        const int col = colb + 8 * j;
        uint32_t h0, l0, h1, l1;
        mk2h(O[j][0] * inv_lo, O[j][1] * inv_lo, h0, l0);
        mk2h(O[j][2] * inv_hi, O[j][3] * inv_hi, h1, l1);
        *(uint32_t*)(atth + row_lo * C_ + col)       = h0;
        *(uint32_t*)(attl + row_lo * C_ + col)       = l0;
        *(uint32_t*)(atth + (row_lo + 8) * C_ + col) = h1;
        *(uint32_t*)(attl + (row_lo + 8) * C_ + col) = l1;
    }
}

// ---------------------------------------------------------------------------
extern "C" void kernel_launch(void* const* d_in, const int* in_sizes, int n_in,
                              void* d_out, int out_size)
{
    const float* x      = (const float*)d_in[0];
    const float* w_qkv  = (const float*)d_in[1];
    const float* b_qkv  = (const float*)d_in[2];
    const float* w_proj = (const float*)d_in[3];
    const float* b_proj = (const float*)d_in[4];
    float* out = (float*)d_out;

    unsigned short *qvh, *qvl, *xh, *xl, *wqh, *wph, *ath, *atl;
    cudaGetSymbolAddress((void**)&qvh, g_qkvh);
    cudaGetSymbolAddress((void**)&qvl, g_qkvl);
    cudaGetSymbolAddress((void**)&xh, g_xh);
    cudaGetSymbolAddress((void**)&xl, g_xl);
    cudaGetSymbolAddress((void**)&wqh, g_wqkvh);
    cudaGetSymbolAddress((void**)&wph, g_wprojh);
    cudaGetSymbolAddress((void**)&ath, g_atth);
    cudaGetSymbolAddress((void**)&atl, g_attl);

    cudaFuncSetAttribute(gemm_mma_kernel,
                         cudaFuncAttributeMaxDynamicSharedMemorySize, GEMM_SMEM);
    cudaFuncSetAttribute(attn_mma_kernel,
                         cudaFuncAttributeMaxDynamicSharedMemorySize, ATTN_SMEM);

    // 0) pack inputs to fp16 splits (weights: hi only)
    pack_split_kernel<<<M_*C_/1024, 256>>>(x, xh, xl);
    transpose_pack_kernel<<<dim3(3*C_/32, C_/32), dim3(32, 8)>>>(w_qkv, wqh, C_, 3*C_);
    transpose_pack_kernel<<<dim3(C_/32, C_/32), dim3(32, 8)>>>(w_proj, wph, C_, C_);

    // 1) qkv = x @ w_qkv + b_qkv  -> split-fp16 qkv
    gemm_mma_kernel<<<dim3(3*C_/128, M_/128), 256, GEMM_SMEM>>>(
        xh, xl, wqh, b_qkv, nullptr, qvh, qvl, M_, 3*C_, C_);

    // 2) tensor-core causal flash attention (fp16) -> split-fp16 att
    attn_mma_kernel<<<dim3(T_/128, B_*H_), 256, ATTN_SMEM>>>(qvh, qvl, ath, atl);

    // 3) out = att @ w_proj + b_proj  -> fp32
    gemm_mma_kernel<<<dim3(C_/128, M_/128), 256, GEMM_SMEM>>>(
        ath, atl, wph, b_proj, out, nullptr, nullptr, M_, C_, C_);
}

// round 13
// speedup vs baseline: 1.9872x; 1.5249x over previous
#include <cuda_runtime.h>
#include <cuda_bf16.h>
#include <cuda_fp16.h>
#include <stdint.h>
#include <math.h>

#define B_ 4
#define T_ 2048
#define C_ 1024
#define H_ 16
#define D_ 64
#define M_ (B_*T_)   // 8192

// ---------------------------------------------------------------------------
// Scratch (allocation-free __device__ globals)
// ---------------------------------------------------------------------------
__device__ unsigned short g_qkvh[25165824];    // qkv hi fp16 [8192][3072]
__device__ unsigned short g_qkvl[25165824];    // qkv lo (Q 2-term in attention)
__device__ unsigned short g_xh[8388608];       // x fp16 [8192][1024]
__device__ unsigned short g_wqkvh[3145728];    // w_qkv^T fp16 [3072][1024]
__device__ unsigned short g_wprojh[1048576];   // w_proj^T fp16 [1024][1024]
__device__ unsigned short g_atth[8388608];     // attention out fp16 [8192][1024]

// ---------------------------------------------------------------------------
// Helpers (sm_103 baseline: ldmatrix, mma.sync, cp.async)
// ---------------------------------------------------------------------------
__device__ __forceinline__ uint32_t smem_u32(const void* p) {
    uint32_t a;
    asm("{ .reg .u64 t; cvta.to.shared.u64 t, %1; cvt.u32.u64 %0, t; }"
        : "=r"(a) : "l"(p));
    return a;
}

__device__ __forceinline__ void ldsm_x4(uint32_t& r0, uint32_t& r1,
                                        uint32_t& r2, uint32_t& r3, uint32_t a) {
    asm volatile("ldmatrix.sync.aligned.m8n8.x4.shared.b16 {%0,%1,%2,%3}, [%4];"
                 : "=r"(r0), "=r"(r1), "=r"(r2), "=r"(r3) : "r"(a));
}

__device__ __forceinline__ void ldsm_x2(uint32_t& r0, uint32_t& r1, uint32_t a) {
    asm volatile("ldmatrix.sync.aligned.m8n8.x2.shared.b16 {%0,%1}, [%2];"
                 : "=r"(r0), "=r"(r1) : "r"(a));
}

__device__ __forceinline__ void ldsm_x4t(uint32_t* r, uint32_t a) {
    asm volatile("ldmatrix.sync.aligned.m8n8.x4.trans.shared.b16 {%0,%1,%2,%3}, [%4];"
                 : "=r"(r[0]), "=r"(r[1]), "=r"(r[2]), "=r"(r[3]) : "r"(a));
}

// fp16 MMA, fp32 accumulate
__device__ __forceinline__ void mma16816h(float* c, const uint32_t* A, const uint32_t* Bv) {
    asm volatile(
        "mma.sync.aligned.m16n8k16.row.col.f32.f16.f16.f32 "
        "{%0,%1,%2,%3}, {%4,%5,%6,%7}, {%8,%9}, {%0,%1,%2,%3};"
        : "+f"(c[0]), "+f"(c[1]), "+f"(c[2]), "+f"(c[3])
        : "r"(A[0]), "r"(A[1]), "r"(A[2]), "r"(A[3]), "r"(Bv[0]), "r"(Bv[1]));
}

__device__ __forceinline__ void cp16(uint32_t dst, const void* src) {
    asm volatile("cp.async.cg.shared.global [%0], [%1], 16;" :: "r"(dst), "l"(src));
}
#define CP_COMMIT() asm volatile("cp.async.commit_group;" ::: "memory")
#define CP_WAIT0()  asm volatile("cp.async.wait_group 0;" ::: "memory")

// pack two fp32 -> f16x2 {lo=p0, hi=p1}
__device__ __forceinline__ uint32_t pack_f16(float p0, float p1) {
    uint32_t r;
    asm("cvt.rn.f16x2.f32 %0, %1, %2;" : "=r"(r) : "f"(p1), "f"(p0));
    return r;
}

// split pair -> f16x2 hi + f16x2 residual
__device__ __forceinline__ void mk2h(float p0, float p1, uint32_t& hi, uint32_t& lo) {
    uint32_t h = pack_f16(p0, p1);
    __half2 hh = *reinterpret_cast<__half2*>(&h);
    float r0 = p0 - __low2float(hh);
    float r1 = p1 - __high2float(hh);
    hi = h;
    lo = pack_f16(r0, r1);
}

// ---------------------------------------------------------------------------
// Prep kernels
// ---------------------------------------------------------------------------
__global__ void __launch_bounds__(256) pack_h_kernel(
    const float* __restrict__ src, unsigned short* __restrict__ dst)
{
    int i = blockIdx.x * 256 + threadIdx.x;
    float4 v = ((const float4*)src)[i];
    ((uint2*)dst)[i] = make_uint2(pack_f16(v.x, v.y), pack_f16(v.z, v.w));
}

// w [K,N] fp32 -> wT fp16 [N,K]
__global__ void __launch_bounds__(256) transpose_pack_kernel(
    const float* __restrict__ w, unsigned short* __restrict__ th, int K, int N)
{
    __shared__ float tile[32][33];
    const int k0 = blockIdx.y * 32, n0 = blockIdx.x * 32;
    const int tx = threadIdx.x, ty = threadIdx.y;   // 32 x 8
    #pragma unroll
    for (int i = 0; i < 32; i += 8)
        tile[ty + i][tx] = w[(size_t)(k0 + ty + i) * N + n0 + tx];
    __syncthreads();
    #pragma unroll
    for (int i = 0; i < 32; i += 8) {
        int n = n0 + ty + i;
        int k = k0 + tx;
        __half hv = __float2half_rn(tile[tx][ty + i]);
        th[(size_t)n * K + k] = reinterpret_cast<unsigned short&>(hv);
    }
}

// ---------------------------------------------------------------------------
// 1-term fp16 mma.sync GEMM: out = A @ B^T + bias.
// BM=BN=128, BK=64, 8 warps (2x4), warp tile 64x32, 2-stage cp.async.
// Stage: A 16K | B 16K = 32KB (128B rows, attention-style swizzle).
// ---------------------------------------------------------------------------
#define GEMM_SMEM (2*32768)

__global__ void __launch_bounds__(256) gemm_mma_kernel(
    const unsigned short* __restrict__ ah, const unsigned short* __restrict__ bh,
    const float* __restrict__ bias, float* __restrict__ outf,
    unsigned short* __restrict__ outh, unsigned short* __restrict__ outl,
    int M, int N, int K)
{
    extern __shared__ char smc[];
    const uint32_t sbase = smem_u32(smc);
    const int tid  = threadIdx.x;
    const int wid  = tid >> 5, lane = tid & 31;
    const int wm   = wid >> 2, wn = wid & 3;
    const int mBase = blockIdx.y * 128;
    const int nBase = blockIdx.x * 128;
    const int nk = K >> 6;                      // BK = 64

    auto off = [](int r, int c) { return r * 128 + ((c ^ (r & 7)) << 4); };

    auto issue = [&](int ks, int stage) {
        const int kb = ks << 6;
        uint32_t pb = sbase + stage * 32768;
        #pragma unroll
        for (int it = 0; it < 4; it++) {
            int idx = it * 256 + tid;
            int r = idx >> 3, c = idx & 7;
            cp16(pb +         off(r, c), ah + (size_t)(mBase + r) * K + kb + c * 8);
            cp16(pb + 16384 + off(r, c), bh + (size_t)(nBase + r) * K + kb + c * 8);
        }
        CP_COMMIT();
    };

    float acc[4][4][4];
    #pragma unroll
    for (int i = 0; i < 4; i++)
        #pragma unroll
        for (int j = 0; j < 4; j++)
            #pragma unroll
            for (int r = 0; r < 4; r++) acc[i][j][r] = 0.f;

    const int la_row = lane & 15;
    const int la_kh  = lane >> 4;
    const int lb_row = lane & 7;
    const int lb_kh  = (lane >> 3) & 1;

    issue(0, 0);

    for (int ks = 0; ks < nk; ks++) {
        const int cur = ks & 1;
        CP_WAIT0();
        __syncthreads();
        if (ks + 1 < nk) issue(ks + 1, cur ^ 1);

        const uint32_t sA = sbase + cur * 32768;
        const uint32_t sB = sA + 16384;

        #pragma unroll
        for (int kk = 0; kk < 4; kk++) {        // 4 k16 per BK=64
            const int ch_a = 2 * kk + la_kh;
            const int ch_b = 2 * kk + lb_kh;

            uint32_t Af[4][4], Bf[4][2];
            #pragma unroll
            for (int i = 0; i < 4; i++) {
                int row = wm * 64 + i * 16 + la_row;
                ldsm_x4(Af[i][0], Af[i][1], Af[i][2], Af[i][3], sA + off(row, ch_a));
            }
            #pragma unroll
            for (int j = 0; j < 4; j++) {
                int row = wn * 32 + j * 8 + lb_row;
                ldsm_x2(Bf[j][0], Bf[j][1], sB + off(row, ch_b));
            }
            #pragma unroll
            for (int i = 0; i < 4; i++)
                #pragma unroll
                for (int j = 0; j < 4; j++) mma16816h(acc[i][j], Af[i], Bf[j]);
        }
    }

    // Epilogue
    const int g = lane >> 2, q = lane & 3;
    #pragma unroll
    for (int i = 0; i < 4; i++) {
        const int row0 = mBase + wm * 64 + i * 16 + g;
        #pragma unroll
        for (int j = 0; j < 4; j++) {
            const int col = nBase + wn * 32 + j * 8 + q * 2;
            float2 bb = *(const float2*)(bias + col);
            float v0x = acc[i][j][0] + bb.x, v0y = acc[i][j][1] + bb.y;
            float v1x = acc[i][j][2] + bb.x, v1y = acc[i][j][3] + bb.y;
            if (outh) {
                uint32_t h0, l0, h1, l1;
                mk2h(v0x, v0y, h0, l0);
                mk2h(v1x, v1y, h1, l1);
                *(uint32_t*)(outh + (size_t)row0 * N + col)       = h0;
                *(uint32_t*)(outl + (size_t)row0 * N + col)       = l0;
                *(uint32_t*)(outh + (size_t)(row0 + 8) * N + col) = h1;
                *(uint32_t*)(outl + (size_t)(row0 + 8) * N + col) = l1;
            } else {
                *(float2*)(outf + (size_t)row0 * N + col)       = make_float2(v0x, v0y);
                *(float2*)(outf + (size_t)(row0 + 8) * N + col) = make_float2(v1x, v1y);
            }
        }
    }
}

// ---------------------------------------------------------------------------
// Tensor-core flash attention (causal, fp16). R12 structure; epilogue
// writes fp16 hi only (proj GEMM is 1-term).
// ---------------------------------------------------------------------------
#define ATTN_SMEM (32768 + 2*16384)

__global__ void __launch_bounds__(256, 2) attn_mma_kernel(
    const unsigned short* __restrict__ qkvh,
    const unsigned short* __restrict__ qkvl,
    unsigned short* __restrict__ atth)
{
    extern __shared__ char smc[];
    const uint32_t sb = smem_u32(smc);
    const int tid = threadIdx.x, lane = tid & 31, w = tid >> 5;
    const int bh = blockIdx.y, b = bh >> 4, hd = bh & 15;
    const int qb = (int)gridDim.x - 1 - (int)blockIdx.x;   // big blocks first
    const int q0 = qb * 128;
    const int nkt = 2 * qb + 2;

    const size_t base = (size_t)b * T_ * 3072 + hd * 64;
    const unsigned short* qh = qkvh + base;
    const unsigned short* qlp = qkvl + base;
    const unsigned short* kh = qh + 1024;
    const unsigned short* vh = qh + 2048;

    const uint32_t sQh = sb, sQl = sb + 16384;
    auto stage0 = [&](int s) { return sb + 32768 + s * 16384; };
    auto off = [](int r, int c) { return r * 128 + ((c ^ (r & 7)) << 4); };

    auto issue_kv = [&](int kt, int s) {
        uint32_t sn = stage0(s);
        const size_t kb = (size_t)kt * 64;
        #pragma unroll
        for (int i = 0; i < 2; i++) {
            int idx = i * 256 + tid;
            int r = idx >> 3, c = idx & 7;
            const size_t g = (kb + r) * 3072 + c * 8;
            cp16(sn +        off(r, c), kh + g);
            cp16(sn + 8192 + off(r, c), vh + g);
        }
        CP_COMMIT();
    };

    // prologue: Q (hi+lo) + K/V tile 0, one commit group
    #pragma unroll
    for (int i = 0; i < 4; i++) {
        int idx = i * 256 + tid;
        int r = idx >> 3, c = idx & 7;
        const size_t g = (size_t)(q0 + r) * 3072 + c * 8;
        cp16(sQh + off(r, c), qh + g);
        cp16(sQl + off(r, c), qlp + g);
    }
    issue_kv(0, 0);

    float O[8][4], s[8][4];
    #pragma unroll
    for (int j = 0; j < 8; j++) { O[j][0] = O[j][1] = O[j][2] = O[j][3] = 0.f; }
    float m_lo = -1e30f, m_hi = -1e30f, l_lo = 0.f, l_hi = 0.f;

    const int la_row = lane & 15, la_kh = lane >> 4;
    const int kb_row = ((lane >> 4) << 3) + (lane & 7);
    const int kb_ch  = (lane >> 3) & 1;
    const int vb_row = (((lane >> 3) & 1) << 3) + (lane & 7);
    const int vb_ch  = lane >> 4;
    const int rowq_lo = q0 + w * 16 + (lane >> 2);
    const float SC = 0.125f * 1.4426950408889634f;   // scale * log2(e)

    for (int kt = 0; kt < nkt; kt++) {
        const int cur = kt & 1;
        CP_WAIT0();
        __syncthreads();
        if (kt + 1 < nkt) issue_kv(kt + 1, cur ^ 1);

        const int k0 = kt * 64;
        const bool active = (k0 <= q0 + w * 16 + 15);
        if (active) {
            const uint32_t cK = stage0(cur);
            const uint32_t cV = cK + 8192;

            // ---- S = Q K^T (fp16 2-term: QhKh + QlKh) ----
            #pragma unroll
            for (int j = 0; j < 8; j++) { s[j][0] = s[j][1] = s[j][2] = s[j][3] = 0.f; }
            #pragma unroll
            for (int kk = 0; kk < 4; kk++) {
                uint32_t aqh[4], aql[4];
                ldsm_x4(aqh[0], aqh[1], aqh[2], aqh[3],
                        sQh + off(w * 16 + la_row, 2 * kk + la_kh));
                ldsm_x4(aql[0], aql[1], aql[2], aql[3],
                        sQl + off(w * 16 + la_row, 2 * kk + la_kh));
                #pragma unroll
                for (int j2 = 0; j2 < 4; j2++) {
                    uint32_t bk[4];
                    ldsm_x4(bk[0], bk[1], bk[2], bk[3],
                            cK + off(16 * j2 + kb_row, 2 * kk + kb_ch));
                    mma16816h(s[2 * j2],     aqh, bk);
                    mma16816h(s[2 * j2 + 1], aqh, bk + 2);
                    mma16816h(s[2 * j2],     aql, bk);
                    mma16816h(s[2 * j2 + 1], aql, bk + 2);
                }
            }

            // ---- online softmax (exp2 domain) ----
            const bool masked = (k0 + 63 > q0 + w * 16);
            float rm_lo = -1e30f, rm_hi = -1e30f;
            #pragma unroll
            for (int j = 0; j < 8; j++) {
                int colb = k0 + 8 * j + 2 * (lane & 3);
                #pragma unroll
                for (int e = 0; e < 2; e++) {
                    float v = s[j][e] * SC;
                    if (masked && (colb + e) > rowq_lo) v = -1e30f;
                    s[j][e] = v; rm_lo = fmaxf(rm_lo, v);
                    float v2 = s[j][2 + e] * SC;
                    if (masked && (colb + e) > rowq_lo + 8) v2 = -1e30f;
                    s[j][2 + e] = v2; rm_hi = fmaxf(rm_hi, v2);
                }
            }
            rm_lo = fmaxf(rm_lo, __shfl_xor_sync(0xffffffffu, rm_lo, 1));
            rm_lo = fmaxf(rm_lo, __shfl_xor_sync(0xffffffffu, rm_lo, 2));
            rm_hi = fmaxf(rm_hi, __shfl_xor_sync(0xffffffffu, rm_hi, 1));
            rm_hi = fmaxf(rm_hi, __shfl_xor_sync(0xffffffffu, rm_hi, 2));
            float mn_lo = fmaxf(m_lo, rm_lo), mn_hi = fmaxf(m_hi, rm_hi);
            float corr_lo = exp2f(m_lo - mn_lo), corr_hi = exp2f(m_hi - mn_hi);
            m_lo = mn_lo; m_hi = mn_hi;
            float ps_lo = 0.f, ps_hi = 0.f;
            #pragma unroll
            for (int j = 0; j < 8; j++) {
                s[j][0] = exp2f(s[j][0] - mn_lo);
                s[j][1] = exp2f(s[j][1] - mn_lo);
                s[j][2] = exp2f(s[j][2] - mn_hi);
                s[j][3] = exp2f(s[j][3] - mn_hi);
                ps_lo += s[j][0] + s[j][1];
                ps_hi += s[j][2] + s[j][3];
            }
            ps_lo += __shfl_xor_sync(0xffffffffu, ps_lo, 1);
            ps_lo += __shfl_xor_sync(0xffffffffu, ps_lo, 2);
            ps_hi += __shfl_xor_sync(0xffffffffu, ps_hi, 1);
            ps_hi += __shfl_xor_sync(0xffffffffu, ps_hi, 2);
            l_lo = l_lo * corr_lo + ps_lo;
            l_hi = l_hi * corr_hi + ps_hi;
            #pragma unroll
            for (int j = 0; j < 8; j++) {
                O[j][0] *= corr_lo; O[j][1] *= corr_lo;
                O[j][2] *= corr_hi; O[j][3] *= corr_hi;
            }

            // ---- O += P V (P fp16 single; V fp16 single) ----
            #pragma unroll
            for (int t = 0; t < 4; t++) {
                uint32_t ph[4];
                ph[0] = pack_f16(s[2 * t][0],     s[2 * t][1]);
                ph[1] = pack_f16(s[2 * t][2],     s[2 * t][3]);
                ph[2] = pack_f16(s[2 * t + 1][0], s[2 * t + 1][1]);
                ph[3] = pack_f16(s[2 * t + 1][2], s[2 * t + 1][3]);
                #pragma unroll
                for (int j2 = 0; j2 < 4; j2++) {
                    uint32_t bv[4];
                    ldsm_x4t(bv, cV + off(16 * t + vb_row, 2 * j2 + vb_ch));
                    mma16816h(O[2 * j2],     ph, bv);
                    mma16816h(O[2 * j2 + 1], ph, bv + 2);
                }
            }
        }
    }

    // ---- epilogue: normalize, fp16, write (hi only) ----
    const float inv_lo = 1.f / l_lo, inv_hi = 1.f / l_hi;
    const size_t row_lo = (size_t)(b * T_) + q0 + w * 16 + (lane >> 2);
    const int colb = hd * 64 + 2 * (lane & 3);
    #pragma unroll
    for (int j = 0; j < 8; j++) {
        const int col = colb + 8 * j;
        *(uint32_t*)(atth + row_lo * C_ + col) =
            pack_f16(O[j][0] * inv_lo, O[j][1] * inv_lo);
        *(uint32_t*)(atth + (row_lo + 8) * C_ + col) =
            pack_f16(O[j][2] * inv_hi, O[j][3] * inv_hi);
    }
}

// ---------------------------------------------------------------------------
extern "C" void kernel_launch(void* const* d_in, const int* in_sizes, int n_in,
                              void* d_out, int out_size)
{
    const float* x      = (const float*)d_in[0];
    const float* w_qkv  = (const float*)d_in[1];
    const float* b_qkv  = (const float*)d_in[2];
    const float* w_proj = (const float*)d_in[3];
    const float* b_proj = (const float*)d_in[4];
    float* out = (float*)d_out;

    unsigned short *qvh, *qvl, *xh, *wqh, *wph, *ath;
    cudaGetSymbolAddress((void**)&qvh, g_qkvh);
    cudaGetSymbolAddress((void**)&qvl, g_qkvl);
    cudaGetSymbolAddress((void**)&xh, g_xh);
    cudaGetSymbolAddress((void**)&wqh, g_wqkvh);
    cudaGetSymbolAddress((void**)&wph, g_wprojh);
    cudaGetSymbolAddress((void**)&ath, g_atth);

    cudaFuncSetAttribute(gemm_mma_kernel,
                         cudaFuncAttributeMaxDynamicSharedMemorySize, GEMM_SMEM);
    cudaFuncSetAttribute(attn_mma_kernel,
                         cudaFuncAttributeMaxDynamicSharedMemorySize, ATTN_SMEM);

    // 0) pack inputs to fp16
    pack_h_kernel<<<M_*C_/1024, 256>>>(x, xh);
    transpose_pack_kernel<<<dim3(3*C_/32, C_/32), dim3(32, 8)>>>(w_qkv, wqh, C_, 3*C_);
    transpose_pack_kernel<<<dim3(C_/32, C_/32), dim3(32, 8)>>>(w_proj, wph, C_, C_);

    // 1) qkv = x @ w_qkv + b_qkv  -> split-fp16 qkv (hi+lo; Q 2-term in attn)
    gemm_mma_kernel<<<dim3(3*C_/128, M_/128), 256, GEMM_SMEM>>>(
        xh, wqh, b_qkv, nullptr, qvh, qvl, M_, 3*C_, C_);

    // 2) tensor-core causal flash attention (fp16) -> fp16 att (hi only)
    attn_mma_kernel<<<dim3(T_/128, B_*H_), 256, ATTN_SMEM>>>(qvh, qvl, ath);

    // 3) out = att @ w_proj + b_proj  -> fp32
    gemm_mma_kernel<<<dim3(C_/128, M_/128), 256, GEMM_SMEM>>>(
        ath, wph, b_proj, out, nullptr, nullptr, M_, C_, C_);
}

// round 15
// speedup vs baseline: 2.2526x; 1.1335x over previous
#include <cuda_runtime.h>
#include <cuda_bf16.h>
#include <cuda_fp16.h>
#include <stdint.h>
#include <math.h>

#define B_ 4
#define T_ 2048
#define C_ 1024
#define H_ 16
#define D_ 64
#define M_ (B_*T_)   // 8192

// ---------------------------------------------------------------------------
// Scratch (allocation-free __device__ globals) — all fp16
// ---------------------------------------------------------------------------
__device__ unsigned short g_qkv[25165824];     // qkv fp16 [8192][3072]
__device__ unsigned short g_xh[8388608];       // x fp16 [8192][1024]
__device__ unsigned short g_wqkvh[3145728];    // w_qkv^T fp16 [3072][1024]
__device__ unsigned short g_wprojh[1048576];   // w_proj^T fp16 [1024][1024]
__device__ unsigned short g_atth[8388608];     // attention out fp16 [8192][1024]

// ---------------------------------------------------------------------------
// Helpers (sm_103 baseline: ldmatrix, mma.sync, cp.async)
// ---------------------------------------------------------------------------
__device__ __forceinline__ uint32_t smem_u32(const void* p) {
    uint32_t a;
    asm("{ .reg .u64 t; cvta.to.shared.u64 t, %1; cvt.u32.u64 %0, t; }"
        : "=r"(a) : "l"(p));
    return a;
}

__device__ __forceinline__ void ldsm_x4(uint32_t& r0, uint32_t& r1,
                                        uint32_t& r2, uint32_t& r3, uint32_t a) {
    asm volatile("ldmatrix.sync.aligned.m8n8.x4.shared.b16 {%0,%1,%2,%3}, [%4];"
                 : "=r"(r0), "=r"(r1), "=r"(r2), "=r"(r3) : "r"(a));
}

__device__ __forceinline__ void ldsm_x2(uint32_t& r0, uint32_t& r1, uint32_t a) {
    asm volatile("ldmatrix.sync.aligned.m8n8.x2.shared.b16 {%0,%1}, [%2];"
                 : "=r"(r0), "=r"(r1) : "r"(a));
}

__device__ __forceinline__ void ldsm_x4t(uint32_t* r, uint32_t a) {
    asm volatile("ldmatrix.sync.aligned.m8n8.x4.trans.shared.b16 {%0,%1,%2,%3}, [%4];"
                 : "=r"(r[0]), "=r"(r[1]), "=r"(r[2]), "=r"(r[3]) : "r"(a));
}

// fp16 MMA, fp32 accumulate
__device__ __forceinline__ void mma16816h(float* c, const uint32_t* A, const uint32_t* Bv) {
    asm volatile(
        "mma.sync.aligned.m16n8k16.row.col.f32.f16.f16.f32 "
        "{%0,%1,%2,%3}, {%4,%5,%6,%7}, {%8,%9}, {%0,%1,%2,%3};"
        : "+f"(c[0]), "+f"(c[1]), "+f"(c[2]), "+f"(c[3])
        : "r"(A[0]), "r"(A[1]), "r"(A[2]), "r"(A[3]), "r"(Bv[0]), "r"(Bv[1]));
}

__device__ __forceinline__ void cp16(uint32_t dst, const void* src) {
    asm volatile("cp.async.cg.shared.global [%0], [%1], 16;" :: "r"(dst), "l"(src));
}
#define CP_COMMIT() asm volatile("cp.async.commit_group;" ::: "memory")
#define CP_WAIT0()  asm volatile("cp.async.wait_group 0;" ::: "memory")

// pack two fp32 -> f16x2 {lo=p0, hi=p1}
__device__ __forceinline__ uint32_t pack_f16(float p0, float p1) {
    uint32_t r;
    asm("cvt.rn.f16x2.f32 %0, %1, %2;" : "=r"(r) : "f"(p1), "f"(p0));
    return r;
}

// ---------------------------------------------------------------------------
// Prep kernels
// ---------------------------------------------------------------------------
__global__ void __launch_bounds__(256) pack_h_kernel(
    const float* __restrict__ src, unsigned short* __restrict__ dst)
{
    int i = blockIdx.x * 256 + threadIdx.x;
    float4 v = ((const float4*)src)[i];
    ((uint2*)dst)[i] = make_uint2(pack_f16(v.x, v.y), pack_f16(v.z, v.w));
}

// w [K,N] fp32 -> wT fp16 [N,K]
__global__ void __launch_bounds__(256) transpose_pack_kernel(
    const float* __restrict__ w, unsigned short* __restrict__ th, int K, int N)
{
    __shared__ float tile[32][33];
    const int k0 = blockIdx.y * 32, n0 = blockIdx.x * 32;
    const int tx = threadIdx.x, ty = threadIdx.y;   // 32 x 8
    #pragma unroll
    for (int i = 0; i < 32; i += 8)
        tile[ty + i][tx] = w[(size_t)(k0 + ty + i) * N + n0 + tx];
    __syncthreads();
    #pragma unroll
    for (int i = 0; i < 32; i += 8) {
        int n = n0 + ty + i;
        int k = k0 + tx;
        __half hv = __float2half_rn(tile[tx][ty + i]);
        th[(size_t)n * K + k] = reinterpret_cast<unsigned short&>(hv);
    }
}

// ---------------------------------------------------------------------------
// 1-term fp16 mma.sync GEMM: out = A @ B^T + bias.
// BM=BN=128, BK=64, 8 warps (2x4), warp tile 64x32, 2-stage cp.async.
// Output: fp16 (outh) or fp32 (outf).
// ---------------------------------------------------------------------------
#define GEMM_SMEM (2*32768)

__global__ void __launch_bounds__(256) gemm_mma_kernel(
    const unsigned short* __restrict__ ah, const unsigned short* __restrict__ bh,
    const float* __restrict__ bias, float* __restrict__ outf,
    unsigned short* __restrict__ outh,
    int M, int N, int K)
{
    extern __shared__ char smc[];
    const uint32_t sbase = smem_u32(smc);
    const int tid  = threadIdx.x;
    const int wid  = tid >> 5, lane = tid & 31;
    const int wm   = wid >> 2, wn = wid & 3;
    const int mBase = blockIdx.y * 128;
    const int nBase = blockIdx.x * 128;
    const int nk = K >> 6;                      // BK = 64

    auto off = [](int r, int c) { return r * 128 + ((c ^ (r & 7)) << 4); };

    auto issue = [&](int ks, int stage) {
        const int kb = ks << 6;
        uint32_t pb = sbase + stage * 32768;
        #pragma unroll
        for (int it = 0; it < 4; it++) {
            int idx = it * 256 + tid;
            int r = idx >> 3, c = idx & 7;
            cp16(pb +         off(r, c), ah + (size_t)(mBase + r) * K + kb + c * 8);
            cp16(pb + 16384 + off(r, c), bh + (size_t)(nBase + r) * K + kb + c * 8);
        }
        CP_COMMIT();
    };

    float acc[4][4][4];
    #pragma unroll
    for (int i = 0; i < 4; i++)
        #pragma unroll
        for (int j = 0; j < 4; j++)
            #pragma unroll
            for (int r = 0; r < 4; r++) acc[i][j][r] = 0.f;

    const int la_row = lane & 15;
    const int la_kh  = lane >> 4;
    const int lb_row = lane & 7;
    const int lb_kh  = (lane >> 3) & 1;

    issue(0, 0);

    for (int ks = 0; ks < nk; ks++) {
        const int cur = ks & 1;
        CP_WAIT0();
        __syncthreads();
        if (ks + 1 < nk) issue(ks + 1, cur ^ 1);

        const uint32_t sA = sbase + cur * 32768;
        const uint32_t sB = sA + 16384;

        #pragma unroll
        for (int kk = 0; kk < 4; kk++) {        // 4 k16 per BK=64
            const int ch_a = 2 * kk + la_kh;
            const int ch_b = 2 * kk + lb_kh;

            uint32_t Af[4][4], Bf[4][2];
            #pragma unroll
            for (int i = 0; i < 4; i++) {
                int row = wm * 64 + i * 16 + la_row;
                ldsm_x4(Af[i][0], Af[i][1], Af[i][2], Af[i][3], sA + off(row, ch_a));
            }
            #pragma unroll
            for (int j = 0; j < 4; j++) {
                int row = wn * 32 + j * 8 + lb_row;
                ldsm_x2(Bf[j][0], Bf[j][1], sB + off(row, ch_b));
            }
            #pragma unroll
            for (int i = 0; i < 4; i++)
                #pragma unroll
                for (int j = 0; j < 4; j++) mma16816h(acc[i][j], Af[i], Bf[j]);
        }
    }

    // Epilogue
    const int g = lane >> 2, q = lane & 3;
    #pragma unroll
    for (int i = 0; i < 4; i++) {
        const int row0 = mBase + wm * 64 + i * 16 + g;
        #pragma unroll
        for (int j = 0; j < 4; j++) {
            const int col = nBase + wn * 32 + j * 8 + q * 2;
            float2 bb = *(const float2*)(bias + col);
            float v0x = acc[i][j][0] + bb.x, v0y = acc[i][j][1] + bb.y;
            float v1x = acc[i][j][2] + bb.x, v1y = acc[i][j][3] + bb.y;
            if (outh) {
                *(uint32_t*)(outh + (size_t)row0 * N + col)       = pack_f16(v0x, v0y);
                *(uint32_t*)(outh + (size_t)(row0 + 8) * N + col) = pack_f16(v1x, v1y);
            } else {
                *(float2*)(outf + (size_t)row0 * N + col)       = make_float2(v0x, v0y);
                *(float2*)(outf + (size_t)(row0 + 8) * N + col) = make_float2(v1x, v1y);
            }
        }
    }
}

// ---------------------------------------------------------------------------
// Tensor-core flash attention (causal, fp16, all single-term).
// S = Q*K (1-term fp16), PV = P*V (1-term fp16).
// Block = 128 q rows, 8 warps (m16), 2-stage K/V pipeline (16KB/stage).
// Smem: Q 16K | 2 x (K 8K | V 8K) = 48KB.
// ---------------------------------------------------------------------------
#define ATTN_SMEM (16384 + 2*16384)

__global__ void __launch_bounds__(256, 2) attn_mma_kernel(
    const unsigned short* __restrict__ qkv,
    unsigned short* __restrict__ atth)
{
    extern __shared__ char smc[];
    const uint32_t sb = smem_u32(smc);
    const int tid = threadIdx.x, lane = tid & 31, w = tid >> 5;
    const int bh = blockIdx.y, b = bh >> 4, hd = bh & 15;
    const int qb = (int)gridDim.x - 1 - (int)blockIdx.x;   // big blocks first
    const int q0 = qb * 128;
    const int nkt = 2 * qb + 2;

    const size_t base = (size_t)b * T_ * 3072 + hd * 64;
    const unsigned short* qh = qkv + base;
    const unsigned short* kh = qh + 1024;
    const unsigned short* vh = qh + 2048;

    const uint32_t sQ = sb;
    auto stage0 = [&](int s) { return sb + 16384 + s * 16384; };
    auto off = [](int r, int c) { return r * 128 + ((c ^ (r & 7)) << 4); };

    auto issue_kv = [&](int kt, int s) {
        uint32_t sn = stage0(s);
        const size_t kb = (size_t)kt * 64;
        #pragma unroll
        for (int i = 0; i < 2; i++) {
            int idx = i * 256 + tid;
            int r = idx >> 3, c = idx & 7;
            const size_t g = (kb + r) * 3072 + c * 8;
            cp16(sn +        off(r, c), kh + g);
            cp16(sn + 8192 + off(r, c), vh + g);
        }
        CP_COMMIT();
    };

    // prologue: Q (128 rows = 1024 chunks -> 4 iterations) + K/V tile 0
    #pragma unroll
    for (int i = 0; i < 4; i++) {
        int idx = i * 256 + tid;
        int r = idx >> 3, c = idx & 7;
        cp16(sQ + off(r, c), qh + (size_t)(q0 + r) * 3072 + c * 8);
    }
    issue_kv(0, 0);

    float O[8][4], s[8][4];
    #pragma unroll
    for (int j = 0; j < 8; j++) { O[j][0] = O[j][1] = O[j][2] = O[j][3] = 0.f; }
    float m_lo = -1e30f, m_hi = -1e30f, l_lo = 0.f, l_hi = 0.f;

    const int la_row = lane & 15, la_kh = lane >> 4;
    const int kb_row = ((lane >> 4) << 3) + (lane & 7);
    const int kb_ch  = (lane >> 3) & 1;
    const int vb_row = (((lane >> 3) & 1) << 3) + (lane & 7);
    const int vb_ch  = lane >> 4;
    const int rowq_lo = q0 + w * 16 + (lane >> 2);
    const float SC = 0.125f * 1.4426950408889634f;   // scale * log2(e)

    for (int kt = 0; kt < nkt; kt++) {
        const int cur = kt & 1;
        CP_WAIT0();
        __syncthreads();
        if (kt + 1 < nkt) issue_kv(kt + 1, cur ^ 1);

        const int k0 = kt * 64;
        const bool active = (k0 <= q0 + w * 16 + 15);
        if (active) {
            const uint32_t cK = stage0(cur);
            const uint32_t cV = cK + 8192;

            // ---- S = Q K^T (fp16 1-term) ----
            #pragma unroll
            for (int j = 0; j < 8; j++) { s[j][0] = s[j][1] = s[j][2] = s[j][3] = 0.f; }
            #pragma unroll
            for (int kk = 0; kk < 4; kk++) {
                uint32_t aq[4];
                ldsm_x4(aq[0], aq[1], aq[2], aq[3],
                        sQ + off(w * 16 + la_row, 2 * kk + la_kh));
                #pragma unroll
                for (int j2 = 0; j2 < 4; j2++) {
                    uint32_t bk[4];
                    ldsm_x4(bk[0], bk[1], bk[2], bk[3],
                            cK + off(16 * j2 + kb_row, 2 * kk + kb_ch));
                    mma16816h(s[2 * j2],     aq, bk);
                    mma16816h(s[2 * j2 + 1], aq, bk + 2);
                }
            }

            // ---- online softmax (exp2 domain) ----
            const bool masked = (k0 + 63 > q0 + w * 16);
            float rm_lo = -1e30f, rm_hi = -1e30f;
            #pragma unroll
            for (int j = 0; j < 8; j++) {
                int colb = k0 + 8 * j + 2 * (lane & 3);
                #pragma unroll
                for (int e = 0; e < 2; e++) {
                    float v = s[j][e] * SC;
                    if (masked && (colb + e) > rowq_lo) v = -1e30f;
                    s[j][e] = v; rm_lo = fmaxf(rm_lo, v);
                    float v2 = s[j][2 + e] * SC;
                    if (masked && (colb + e) > rowq_lo + 8) v2 = -1e30f;
                    s[j][2 + e] = v2; rm_hi = fmaxf(rm_hi, v2);
                }
            }
            rm_lo = fmaxf(rm_lo, __shfl_xor_sync(0xffffffffu, rm_lo, 1));
            rm_lo = fmaxf(rm_lo, __shfl_xor_sync(0xffffffffu, rm_lo, 2));
            rm_hi = fmaxf(rm_hi, __shfl_xor_sync(0xffffffffu, rm_hi, 1));
            rm_hi = fmaxf(rm_hi, __shfl_xor_sync(0xffffffffu, rm_hi, 2));
            float mn_lo = fmaxf(m_lo, rm_lo), mn_hi = fmaxf(m_hi, rm_hi);
            float corr_lo = exp2f(m_lo - mn_lo), corr_hi = exp2f(m_hi - mn_hi);
            m_lo = mn_lo; m_hi = mn_hi;
            float ps_lo = 0.f, ps_hi = 0.f;
            #pragma unroll
            for (int j = 0; j < 8; j++) {
                s[j][0] = exp2f(s[j][0] - mn_lo);
                s[j][1] = exp2f(s[j][1] - mn_lo);
                s[j][2] = exp2f(s[j][2] - mn_hi);
                s[j][3] = exp2f(s[j][3] - mn_hi);
                ps_lo += s[j][0] + s[j][1];
                ps_hi += s[j][2] + s[j][3];
            }
            ps_lo += __shfl_xor_sync(0xffffffffu, ps_lo, 1);
            ps_lo += __shfl_xor_sync(0xffffffffu, ps_lo, 2);
            ps_hi += __shfl_xor_sync(0xffffffffu, ps_hi, 1);
            ps_hi += __shfl_xor_sync(0xffffffffu, ps_hi, 2);
            l_lo = l_lo * corr_lo + ps_lo;
            l_hi = l_hi * corr_hi + ps_hi;
            #pragma unroll
            for (int j = 0; j < 8; j++) {
                O[j][0] *= corr_lo; O[j][1] *= corr_lo;
                O[j][2] *= corr_hi; O[j][3] *= corr_hi;
            }

            // ---- O += P V (both fp16 1-term) ----
            #pragma unroll
            for (int t = 0; t < 4; t++) {
                uint32_t ph[4];
                ph[0] = pack_f16(s[2 * t][0],     s[2 * t][1]);
                ph[1] = pack_f16(s[2 * t][2],     s[2 * t][3]);
                ph[2] = pack_f16(s[2 * t + 1][0], s[2 * t + 1][1]);
                ph[3] = pack_f16(s[2 * t + 1][2], s[2 * t + 1][3]);
                #pragma unroll
                for (int j2 = 0; j2 < 4; j2++) {
                    uint32_t bv[4];
                    ldsm_x4t(bv, cV + off(16 * t + vb_row, 2 * j2 + vb_ch));
                    mma16816h(O[2 * j2],     ph, bv);
                    mma16816h(O[2 * j2 + 1], ph, bv + 2);
                }
            }
        }
    }

    // ---- epilogue: normalize, fp16, write ----
    const float inv_lo = 1.f / l_lo, inv_hi = 1.f / l_hi;
    const size_t row_lo = (size_t)(b * T_) + q0 + w * 16 + (lane >> 2);
    const int colb = hd * 64 + 2 * (lane & 3);
    #pragma unroll
    for (int j = 0; j < 8; j++) {
        const int col = colb + 8 * j;
        *(uint32_t*)(atth + row_lo * C_ + col) =
            pack_f16(O[j][0] * inv_lo, O[j][1] * inv_lo);
        *(uint32_t*)(atth + (row_lo + 8) * C_ + col) =
            pack_f16(O[j][2] * inv_hi, O[j][3] * inv_hi);
    }
}

// ---------------------------------------------------------------------------
extern "C" void kernel_launch(void* const* d_in, const int* in_sizes, int n_in,
                              void* d_out, int out_size)
{
    const float* x      = (const float*)d_in[0];
    const float* w_qkv  = (const float*)d_in[1];
    const float* b_qkv  = (const float*)d_in[2];
    const float* w_proj = (const float*)d_in[3];
    const float* b_proj = (const float*)d_in[4];
    float* out = (float*)d_out;

    unsigned short *qv, *xh, *wqh, *wph, *ath;
    cudaGetSymbolAddress((void**)&qv, g_qkv);
    cudaGetSymbolAddress((void**)&xh, g_xh);
    cudaGetSymbolAddress((void**)&wqh, g_wqkvh);
    cudaGetSymbolAddress((void**)&wph, g_wprojh);
    cudaGetSymbolAddress((void**)&ath, g_atth);

    cudaFuncSetAttribute(gemm_mma_kernel,
                         cudaFuncAttributeMaxDynamicSharedMemorySize, GEMM_SMEM);
    cudaFuncSetAttribute(attn_mma_kernel,
                         cudaFuncAttributeMaxDynamicSharedMemorySize, ATTN_SMEM);

    // 0) pack inputs to fp16
    pack_h_kernel<<<M_*C_/1024, 256>>>(x, xh);
    transpose_pack_kernel<<<dim3(3*C_/32, C_/32), dim3(32, 8)>>>(w_qkv, wqh, C_, 3*C_);
    transpose_pack_kernel<<<dim3(C_/32, C_/32), dim3(32, 8)>>>(w_proj, wph, C_, C_);

    // 1) qkv = x @ w_qkv + b_qkv  -> fp16 qkv
    gemm_mma_kernel<<<dim3(3*C_/128, M_/128), 256, GEMM_SMEM>>>(
        xh, wqh, b_qkv, nullptr, qv, M_, 3*C_, C_);

    // 2) tensor-core causal flash attention (fp16) -> fp16 att
    attn_mma_kernel<<<dim3(T_/128, B_*H_), 256, ATTN_SMEM>>>(qv, ath);

    // 3) out = att @ w_proj + b_proj  -> fp32
    gemm_mma_kernel<<<dim3(C_/128, M_/128), 256, GEMM_SMEM>>>(
        ath, wph, b_proj, out, nullptr, M_, C_, C_);
}

// round 16
// speedup vs baseline: 2.2744x; 1.0097x over previous
#include <cuda_runtime.h>
#include <cuda_bf16.h>
#include <cuda_fp16.h>
#include <stdint.h>
#include <math.h>

#define B_ 4
#define T_ 2048
#define C_ 1024
#define H_ 16
#define D_ 64
#define M_ (B_*T_)   // 8192

// ---------------------------------------------------------------------------
// Scratch (allocation-free __device__ globals) — all fp16
// ---------------------------------------------------------------------------
__device__ unsigned short g_qkv[25165824];     // qkv fp16 [8192][3072]
__device__ unsigned short g_xh[8388608];       // x fp16 [8192][1024]
__device__ unsigned short g_wqkvh[3145728];    // w_qkv^T fp16 [3072][1024]
__device__ unsigned short g_wprojh[1048576];   // w_proj^T fp16 [1024][1024]
__device__ unsigned short g_atth[8388608];     // attention out fp16 [8192][1024]

// ---------------------------------------------------------------------------
// Helpers (sm_103 baseline: ldmatrix, mma.sync, cp.async)
// ---------------------------------------------------------------------------
__device__ __forceinline__ uint32_t smem_u32(const void* p) {
    uint32_t a;
    asm("{ .reg .u64 t; cvta.to.shared.u64 t, %1; cvt.u32.u64 %0, t; }"
        : "=r"(a) : "l"(p));
    return a;
}

__device__ __forceinline__ void ldsm_x4(uint32_t& r0, uint32_t& r1,
                                        uint32_t& r2, uint32_t& r3, uint32_t a) {
    asm volatile("ldmatrix.sync.aligned.m8n8.x4.shared.b16 {%0,%1,%2,%3}, [%4];"
                 : "=r"(r0), "=r"(r1), "=r"(r2), "=r"(r3) : "r"(a));
}

__device__ __forceinline__ void ldsm_x2(uint32_t& r0, uint32_t& r1, uint32_t a) {
    asm volatile("ldmatrix.sync.aligned.m8n8.x2.shared.b16 {%0,%1}, [%2];"
                 : "=r"(r0), "=r"(r1) : "r"(a));
}

__device__ __forceinline__ void ldsm_x4t(uint32_t* r, uint32_t a) {
    asm volatile("ldmatrix.sync.aligned.m8n8.x4.trans.shared.b16 {%0,%1,%2,%3}, [%4];"
                 : "=r"(r[0]), "=r"(r[1]), "=r"(r[2]), "=r"(r[3]) : "r"(a));
}

// fp16 MMA, fp32 accumulate
__device__ __forceinline__ void mma16816h(float* c, const uint32_t* A, const uint32_t* Bv) {
    asm volatile(
        "mma.sync.aligned.m16n8k16.row.col.f32.f16.f16.f32 "
        "{%0,%1,%2,%3}, {%4,%5,%6,%7}, {%8,%9}, {%0,%1,%2,%3};"
        : "+f"(c[0]), "+f"(c[1]), "+f"(c[2]), "+f"(c[3])
        : "r"(A[0]), "r"(A[1]), "r"(A[2]), "r"(A[3]), "r"(Bv[0]), "r"(Bv[1]));
}

__device__ __forceinline__ void cp16(uint32_t dst, const void* src) {
    asm volatile("cp.async.cg.shared.global [%0], [%1], 16;" :: "r"(dst), "l"(src));
}
#define CP_COMMIT() asm volatile("cp.async.commit_group;" ::: "memory")
#define CP_WAIT0()  asm volatile("cp.async.wait_group 0;" ::: "memory")

// pack two fp32 -> f16x2 {lo=p0, hi=p1}
__device__ __forceinline__ uint32_t pack_f16(float p0, float p1) {
    uint32_t r;
    asm("cvt.rn.f16x2.f32 %0, %1, %2;" : "=r"(r) : "f"(p1), "f"(p0));
    return r;
}

// ---------------------------------------------------------------------------
// Prep kernels
// ---------------------------------------------------------------------------
__global__ void __launch_bounds__(256) pack_h_kernel(
    const float* __restrict__ src, unsigned short* __restrict__ dst)
{
    int i = blockIdx.x * 256 + threadIdx.x;
    float4 v = ((const float4*)src)[i];
    ((uint2*)dst)[i] = make_uint2(pack_f16(v.x, v.y), pack_f16(v.z, v.w));
}

// w [K,N] fp32 -> wT fp16 [N,K]
__global__ void __launch_bounds__(256) transpose_pack_kernel(
    const float* __restrict__ w, unsigned short* __restrict__ th, int K, int N)
{
    __shared__ float tile[32][33];
    const int k0 = blockIdx.y * 32, n0 = blockIdx.x * 32;
    const int tx = threadIdx.x, ty = threadIdx.y;   // 32 x 8
    #pragma unroll
    for (int i = 0; i < 32; i += 8)
        tile[ty + i][tx] = w[(size_t)(k0 + ty + i) * N + n0 + tx];
    __syncthreads();
    #pragma unroll
    for (int i = 0; i < 32; i += 8) {
        int n = n0 + ty + i;
        int k = k0 + tx;
        __half hv = __float2half_rn(tile[tx][ty + i]);
        th[(size_t)n * K + k] = reinterpret_cast<unsigned short&>(hv);
    }
}

// ---------------------------------------------------------------------------
// 1-term fp16 mma.sync GEMM: out = A @ B^T + bias.  (R15 — measured best)
// ---------------------------------------------------------------------------
#define GEMM_SMEM (2*32768)

__global__ void __launch_bounds__(256) gemm_mma_kernel(
    const unsigned short* __restrict__ ah, const unsigned short* __restrict__ bh,
    const float* __restrict__ bias, float* __restrict__ outf,
    unsigned short* __restrict__ outh,
    int M, int N, int K)
{
    extern __shared__ char smc[];
    const uint32_t sbase = smem_u32(smc);
    const int tid  = threadIdx.x;
    const int wid  = tid >> 5, lane = tid & 31;
    const int wm   = wid >> 2, wn = wid & 3;
    const int mBase = blockIdx.y * 128;
    const int nBase = blockIdx.x * 128;
    const int nk = K >> 6;                      // BK = 64

    auto off = [](int r, int c) { return r * 128 + ((c ^ (r & 7)) << 4); };

    auto issue = [&](int ks, int stage) {
        const int kb = ks << 6;
        uint32_t pb = sbase + stage * 32768;
        #pragma unroll
        for (int it = 0; it < 4; it++) {
            int idx = it * 256 + tid;
            int r = idx >> 3, c = idx & 7;
            cp16(pb +         off(r, c), ah + (size_t)(mBase + r) * K + kb + c * 8);
            cp16(pb + 16384 + off(r, c), bh + (size_t)(nBase + r) * K + kb + c * 8);
        }
        CP_COMMIT();
    };

    float acc[4][4][4];
    #pragma unroll
    for (int i = 0; i < 4; i++)
        #pragma unroll
        for (int j = 0; j < 4; j++)
            #pragma unroll
            for (int r = 0; r < 4; r++) acc[i][j][r] = 0.f;

    const int la_row = lane & 15;
    const int la_kh  = lane >> 4;
    const int lb_row = lane & 7;
    const int lb_kh  = (lane >> 3) & 1;

    issue(0, 0);

    for (int ks = 0; ks < nk; ks++) {
        const int cur = ks & 1;
        CP_WAIT0();
        __syncthreads();
        if (ks + 1 < nk) issue(ks + 1, cur ^ 1);

        const uint32_t sA = sbase + cur * 32768;
        const uint32_t sB = sA + 16384;

        #pragma unroll
        for (int kk = 0; kk < 4; kk++) {        // 4 k16 per BK=64
            const int ch_a = 2 * kk + la_kh;
            const int ch_b = 2 * kk + lb_kh;

            uint32_t Af[4][4], Bf[4][2];
            #pragma unroll
            for (int i = 0; i < 4; i++) {
                int row = wm * 64 + i * 16 + la_row;
                ldsm_x4(Af[i][0], Af[i][1], Af[i][2], Af[i][3], sA + off(row, ch_a));
            }
            #pragma unroll
            for (int j = 0; j < 4; j++) {
                int row = wn * 32 + j * 8 + lb_row;
                ldsm_x2(Bf[j][0], Bf[j][1], sB + off(row, ch_b));
            }
            #pragma unroll
            for (int i = 0; i < 4; i++)
                #pragma unroll
                for (int j = 0; j < 4; j++) mma16816h(acc[i][j], Af[i], Bf[j]);
        }
    }

    // Epilogue
    const int g = lane >> 2, q = lane & 3;
    #pragma unroll
    for (int i = 0; i < 4; i++) {
        const int row0 = mBase + wm * 64 + i * 16 + g;
        #pragma unroll
        for (int j = 0; j < 4; j++) {
            const int col = nBase + wn * 32 + j * 8 + q * 2;
            float2 bb = *(const float2*)(bias + col);
            float v0x = acc[i][j][0] + bb.x, v0y = acc[i][j][1] + bb.y;
            float v1x = acc[i][j][2] + bb.x, v1y = acc[i][j][3] + bb.y;
            if (outh) {
                *(uint32_t*)(outh + (size_t)row0 * N + col)       = pack_f16(v0x, v0y);
                *(uint32_t*)(outh + (size_t)(row0 + 8) * N + col) = pack_f16(v1x, v1y);
            } else {
                *(float2*)(outf + (size_t)row0 * N + col)       = make_float2(v0x, v0y);
                *(float2*)(outf + (size_t)(row0 + 8) * N + col) = make_float2(v1x, v1y);
            }
        }
    }
}

// ---------------------------------------------------------------------------
// Tensor-core flash attention (causal, fp16, 1-term).
// K-tile 128 (two 64-col halves per load/barrier); Q fragments register-
// resident and pre-scaled by 0.125*log2(e).
// Smem: Q 16K | 2 stages x (K 16K | V 16K) = 80KB -> 2 CTAs/SM.
// ---------------------------------------------------------------------------
#define ATTN_SMEM (16384 + 2*32768)

__global__ void __launch_bounds__(256, 2) attn_mma_kernel(
    const unsigned short* __restrict__ qkv,
    unsigned short* __restrict__ atth)
{
    extern __shared__ char smc[];
    const uint32_t sb = smem_u32(smc);
    const int tid = threadIdx.x, lane = tid & 31, w = tid >> 5;
    const int bh = blockIdx.y, b = bh >> 4, hd = bh & 15;
    const int qb = (int)gridDim.x - 1 - (int)blockIdx.x;   // big blocks first
    const int q0 = qb * 128;
    const int nkt2 = qb + 1;                                // 128-col tiles

    const size_t base = (size_t)b * T_ * 3072 + hd * 64;
    const unsigned short* qh = qkv + base;
    const unsigned short* kh = qh + 1024;
    const unsigned short* vh = qh + 2048;

    const uint32_t sQ = sb;
    auto stage0 = [&](int s) { return sb + 16384 + s * 32768; };
    auto off = [](int r, int c) { return r * 128 + ((c ^ (r & 7)) << 4); };

    // load K/V 128 rows into stage s (K halves at 0/8K, V halves at 16K/24K)
    auto issue_kv = [&](int kt2, int s) {
        uint32_t sn = stage0(s);
        const size_t kb = (size_t)kt2 * 128;
        #pragma unroll
        for (int i = 0; i < 4; i++) {
            int idx = i * 256 + tid;
            int r = idx >> 3, c = idx & 7;         // r 0..127
            uint32_t hb = (uint32_t)(r >> 6) * 8192;
            int rl = r & 63;
            const size_t g = (kb + r) * 3072 + c * 8;
            cp16(sn + hb +         off(rl, c), kh + g);
            cp16(sn + hb + 16384 + off(rl, c), vh + g);
        }
        CP_COMMIT();
    };

    // prologue: Q (128 rows) + K/V tile 0, one commit group
    #pragma unroll
    for (int i = 0; i < 4; i++) {
        int idx = i * 256 + tid;
        int r = idx >> 3, c = idx & 7;
        cp16(sQ + off(r, c), qh + (size_t)(q0 + r) * 3072 + c * 8);
    }
    issue_kv(0, 0);

    const int la_row = lane & 15, la_kh = lane >> 4;
    const int kb_row = ((lane >> 4) << 3) + (lane & 7);
    const int kb_ch  = (lane >> 3) & 1;
    const int vb_row = (((lane >> 3) & 1) << 3) + (lane & 7);
    const int vb_ch  = lane >> 4;
    const int rowq_lo = q0 + w * 16 + (lane >> 2);

    CP_WAIT0();
    __syncthreads();

    // hoist Q fragments (invariant across the whole KV loop), pre-scaled
    uint32_t aq[4][4];
    {
        const __half2 sc2 = __float2half2_rn(0.1803368801111243f); // 0.125*log2e
        #pragma unroll
        for (int kk = 0; kk < 4; kk++) {
            ldsm_x4(aq[kk][0], aq[kk][1], aq[kk][2], aq[kk][3],
                    sQ + off(w * 16 + la_row, 2 * kk + la_kh));
            #pragma unroll
            for (int r = 0; r < 4; r++) {
                __half2 hv = *reinterpret_cast<__half2*>(&aq[kk][r]);
                hv = __hmul2(hv, sc2);
                aq[kk][r] = *reinterpret_cast<uint32_t*>(&hv);
            }
        }
    }

    float O[8][4], s[8][4];
    #pragma unroll
    for (int j = 0; j < 8; j++) { O[j][0] = O[j][1] = O[j][2] = O[j][3] = 0.f; }
    float m_lo = -1e30f, m_hi = -1e30f, l_lo = 0.f, l_hi = 0.f;

    for (int kt2 = 0; kt2 < nkt2; kt2++) {
        if (kt2 > 0) {
            CP_WAIT0();
            __syncthreads();
        }
        if (kt2 + 1 < nkt2) issue_kv(kt2 + 1, (kt2 + 1) & 1);
        const uint32_t stg = stage0(kt2 & 1);

        #pragma unroll
        for (int half = 0; half < 2; half++) {
            const int k0 = kt2 * 128 + half * 64;
            const bool active = (k0 <= q0 + w * 16 + 15);
            if (!active) continue;
            const uint32_t cK = stg + half * 8192;
            const uint32_t cV = stg + 16384 + half * 8192;

            // ---- S = Q K^T (fp16 1-term, Q pre-scaled) ----
            #pragma unroll
            for (int j = 0; j < 8; j++) { s[j][0] = s[j][1] = s[j][2] = s[j][3] = 0.f; }
            #pragma unroll
            for (int kk = 0; kk < 4; kk++) {
                #pragma unroll
                for (int j2 = 0; j2 < 4; j2++) {
                    uint32_t bk[4];
                    ldsm_x4(bk[0], bk[1], bk[2], bk[3],
                            cK + off(16 * j2 + kb_row, 2 * kk + kb_ch));
                    mma16816h(s[2 * j2],     aq[kk], bk);
                    mma16816h(s[2 * j2 + 1], aq[kk], bk + 2);
                }
            }

            // ---- online softmax (exp2 domain; S pre-scaled) ----
            const bool masked = (k0 + 63 > q0 + w * 16);
            float rm_lo = -1e30f, rm_hi = -1e30f;
            #pragma unroll
            for (int j = 0; j < 8; j++) {
                int colb = k0 + 8 * j + 2 * (lane & 3);
                #pragma unroll
                for (int e = 0; e < 2; e++) {
                    float v = s[j][e];
                    if (masked && (colb + e) > rowq_lo) v = -1e30f;
                    s[j][e] = v; rm_lo = fmaxf(rm_lo, v);
                    float v2 = s[j][2 + e];
                    if (masked && (colb + e) > rowq_lo + 8) v2 = -1e30f;
                    s[j][2 + e] = v2; rm_hi = fmaxf(rm_hi, v2);
                }
            }
            rm_lo = fmaxf(rm_lo, __shfl_xor_sync(0xffffffffu, rm_lo, 1));
            rm_lo = fmaxf(rm_lo, __shfl_xor_sync(0xffffffffu, rm_lo, 2));
            rm_hi = fmaxf(rm_hi, __shfl_xor_sync(0xffffffffu, rm_hi, 1));
            rm_hi = fmaxf(rm_hi, __shfl_xor_sync(0xffffffffu, rm_hi, 2));
            float mn_lo = fmaxf(m_lo, rm_lo), mn_hi = fmaxf(m_hi, rm_hi);
            float corr_lo = exp2f(m_lo - mn_lo), corr_hi = exp2f(m_hi - mn_hi);
            m_lo = mn_lo; m_hi = mn_hi;
            float ps_lo = 0.f, ps_hi = 0.f;
            #pragma unroll
            for (int j = 0; j < 8; j++) {
                s[j][0] = exp2f(s[j][0] - mn_lo);
                s[j][1] = exp2f(s[j][1] - mn_lo);
                s[j][2] = exp2f(s[j][2] - mn_hi);
                s[j][3] = exp2f(s[j][3] - mn_hi);
                ps_lo += s[j][0] + s[j][1];
                ps_hi += s[j][2] + s[j][3];
            }
            ps_lo += __shfl_xor_sync(0xffffffffu, ps_lo, 1);
            ps_lo += __shfl_xor_sync(0xffffffffu, ps_lo, 2);
            ps_hi += __shfl_xor_sync(0xffffffffu, ps_hi, 1);
            ps_hi += __shfl_xor_sync(0xffffffffu, ps_hi, 2);
            l_lo = l_lo * corr_lo + ps_lo;
            l_hi = l_hi * corr_hi + ps_hi;
            #pragma unroll
            for (int j = 0; j < 8; j++) {
                O[j][0] *= corr_lo; O[j][1] *= corr_lo;
                O[j][2] *= corr_hi; O[j][3] *= corr_hi;
            }

            // ---- O += P V (both fp16 1-term) ----
            #pragma unroll
            for (int t = 0; t < 4; t++) {
                uint32_t ph[4];
                ph[0] = pack_f16(s[2 * t][0],     s[2 * t][1]);
                ph[1] = pack_f16(s[2 * t][2],     s[2 * t][3]);
                ph[2] = pack_f16(s[2 * t + 1][0], s[2 * t + 1][1]);
                ph[3] = pack_f16(s[2 * t + 1][2], s[2 * t + 1][3]);
                #pragma unroll
                for (int j2 = 0; j2 < 4; j2++) {
                    uint32_t bv[4];
                    ldsm_x4t(bv, cV + off(16 * t + vb_row, 2 * j2 + vb_ch));
                    mma16816h(O[2 * j2],     ph, bv);
                    mma16816h(O[2 * j2 + 1], ph, bv + 2);
                }
            }
        }
    }

    // ---- epilogue: normalize, fp16, write ----
    const float inv_lo = 1.f / l_lo, inv_hi = 1.f / l_hi;
    const size_t row_lo = (size_t)(b * T_) + q0 + w * 16 + (lane >> 2);
    const int colb = hd * 64 + 2 * (lane & 3);
    #pragma unroll
    for (int j = 0; j < 8; j++) {
        const int col = colb + 8 * j;
        *(uint32_t*)(atth + row_lo * C_ + col) =
            pack_f16(O[j][0] * inv_lo, O[j][1] * inv_lo);
        *(uint32_t*)(atth + (row_lo + 8) * C_ + col) =
            pack_f16(O[j][2] * inv_hi, O[j][3] * inv_hi);
    }
}

// ---------------------------------------------------------------------------
extern "C" void kernel_launch(void* const* d_in, const int* in_sizes, int n_in,
                              void* d_out, int out_size)
{
    const float* x      = (const float*)d_in[0];
    const float* w_qkv  = (const float*)d_in[1];
    const float* b_qkv  = (const float*)d_in[2];
    const float* w_proj = (const float*)d_in[3];
    const float* b_proj = (const float*)d_in[4];
    float* out = (float*)d_out;

    unsigned short *qv, *xh, *wqh, *wph, *ath;
    cudaGetSymbolAddress((void**)&qv, g_qkv);
    cudaGetSymbolAddress((void**)&xh, g_xh);
    cudaGetSymbolAddress((void**)&wqh, g_wqkvh);
    cudaGetSymbolAddress((void**)&wph, g_wprojh);
    cudaGetSymbolAddress((void**)&ath, g_atth);

    cudaFuncSetAttribute(gemm_mma_kernel,
                         cudaFuncAttributeMaxDynamicSharedMemorySize, GEMM_SMEM);
    cudaFuncSetAttribute(attn_mma_kernel,
                         cudaFuncAttributeMaxDynamicSharedMemorySize, ATTN_SMEM);

    // 0) pack inputs to fp16
    pack_h_kernel<<<M_*C_/1024, 256>>>(x, xh);
    transpose_pack_kernel<<<dim3(3*C_/32, C_/32), dim3(32, 8)>>>(w_qkv, wqh, C_, 3*C_);
    transpose_pack_kernel<<<dim3(C_/32, C_/32), dim3(32, 8)>>>(w_proj, wph, C_, C_);

    // 1) qkv = x @ w_qkv + b_qkv  -> fp16 qkv
    gemm_mma_kernel<<<dim3(3*C_/128, M_/128), 256, GEMM_SMEM>>>(
        xh, wqh, b_qkv, nullptr, qv, M_, 3*C_, C_);

    // 2) tensor-core causal flash attention (fp16) -> fp16 att
    attn_mma_kernel<<<dim3(T_/128, B_*H_), 256, ATTN_SMEM>>>(qv, ath);

    // 3) out = att @ w_proj + b_proj  -> fp32
    gemm_mma_kernel<<<dim3(C_/128, M_/128), 256, GEMM_SMEM>>>(
        ath, wph, b_proj, out, nullptr, M_, C_, C_);
}